// round 8
// baseline (speedup 1.0000x reference)
#include <cuda_runtime.h>
#include <cuda_bf16.h>
#include <cstdint>

#define BATCH 32
#define MN    1024
#define DF    128
#define ED    64
#define NROWS (BATCH*MN)   // 32768

// ---------------- device scratch (no runtime allocation allowed) ----------------
__device__ __nv_bfloat16 g_Sh[(size_t)BATCH*MN*MN];   // 64 MB: hi plane of S
__device__ __nv_bfloat16 g_Sl[(size_t)BATCH*MN*MN];   // 64 MB: lo plane of S
__device__ float         g_degp[NROWS*32];
__device__ float         g_dinv[NROWS];
__device__ float         g_z  [(size_t)NROWS*DF];     // Z fp32 row-major (identity term)
__device__ __nv_bfloat16 g_zth[(size_t)BATCH*DF*MN];  // Z^T hi plane [g][d][n]
__device__ __nv_bfloat16 g_ztl[(size_t)BATCH*DF*MN];  // Z^T lo plane
__device__ float         g_y  [(size_t)NROWS*DF];     // layer-1 output fp32

// ---------------- helpers ----------------
__device__ __forceinline__ uint32_t smem_u32(const void* p){
    uint32_t a;
    asm("{ .reg .u64 t; cvta.to.shared.u64 t, %1; cvt.u32.u64 %0, t; }" : "=r"(a) : "l"(p));
    return a;
}
__device__ __forceinline__ void cpa16(uint32_t d, const void* s){
    asm volatile("cp.async.cg.shared.global [%0], [%1], 16;" :: "r"(d), "l"(s));
}
#define CP_COMMIT() asm volatile("cp.async.commit_group;" ::: "memory")
#define CP_WAIT(n)  asm volatile("cp.async.wait_group %0;" :: "n"(n) : "memory")

// bf16 2-term split of a pair (v0 -> low half, v1 -> high half of each packed reg).
__device__ __forceinline__ void bsplit2(float v0, float v1, uint32_t& h01, uint32_t& l01){
    asm("cvt.rn.bf16x2.f32 %0, %1, %2;" : "=r"(h01) : "f"(v1), "f"(v0));
    float h0 = __uint_as_float(h01 << 16);
    float h1 = __uint_as_float(h01 & 0xFFFF0000u);
    float l0 = v0 - h0, l1 = v1 - h1;
    asm("cvt.rn.bf16x2.f32 %0, %1, %2;" : "=r"(l01) : "f"(l1), "f"(l0));
}

__device__ __forceinline__ void mma16(float c[4], const uint32_t a[4], const uint32_t b[2]){
    asm volatile(
        "mma.sync.aligned.m16n8k16.row.col.f32.bf16.bf16.f32 "
        "{%0,%1,%2,%3}, {%4,%5,%6,%7}, {%8,%9}, {%0,%1,%2,%3};"
        : "+f"(c[0]), "+f"(c[1]), "+f"(c[2]), "+f"(c[3])
        : "r"(a[0]), "r"(a[1]), "r"(a[2]), "r"(a[3]), "r"(b[0]), "r"(b[1]));
}

__device__ __forceinline__ void mma3pass(float c[4][4][4],
    const uint32_t ah[4][4], const uint32_t al[4][4],
    const uint32_t bh[4][2], const uint32_t bl[4][2])
{
    #pragma unroll
    for (int j = 0; j < 4; j++)
        #pragma unroll
        for (int i = 0; i < 4; i++) mma16(c[i][j], ah[i], bh[j]);
    #pragma unroll
    for (int j = 0; j < 4; j++)
        #pragma unroll
        for (int i = 0; i < 4; i++) mma16(c[i][j], al[i], bh[j]);
    #pragma unroll
    for (int j = 0; j < 4; j++)
        #pragma unroll
        for (int i = 0; i < 4; i++) mma16(c[i][j], ah[i], bl[j]);
}

// One k16 step from fp32 smem tiles (A [m][k] pitch PA, B [n][k] pitch PB).
template<int PA, int PB>
__device__ __forceinline__ void mma_step_f32(const float* __restrict__ As,
                                             const float* __restrict__ Bs,
                                             int kk, int wy, int wx, int lane,
                                             float c[4][4][4])
{
    const int g = lane >> 2, t = lane & 3;
    uint32_t ah[4][4], al[4][4], bh[4][2], bl[4][2];
    #pragma unroll
    for (int i = 0; i < 4; i++){
        const float* ap = As + (wy*64 + i*16 + g)*PA + kk + 2*t;
        float2 v;
        v = *(const float2*)(ap);            bsplit2(v.x, v.y, ah[i][0], al[i][0]);
        v = *(const float2*)(ap + 8*PA);     bsplit2(v.x, v.y, ah[i][1], al[i][1]);
        v = *(const float2*)(ap + 8);        bsplit2(v.x, v.y, ah[i][2], al[i][2]);
        v = *(const float2*)(ap + 8*PA + 8); bsplit2(v.x, v.y, ah[i][3], al[i][3]);
    }
    #pragma unroll
    for (int j = 0; j < 4; j++){
        const float* bp = Bs + (wx*32 + j*8 + g)*PB + kk + 2*t;
        float2 v;
        v = *(const float2*)(bp);     bsplit2(v.x, v.y, bh[j][0], bl[j][0]);
        v = *(const float2*)(bp + 8); bsplit2(v.x, v.y, bh[j][1], bl[j][1]);
    }
    mma3pass(c, ah, al, bh, bl);
}

// One k16 step from pre-split bf16 planes, pitch P elems.
template<int P>
__device__ __forceinline__ void mma_step_bf16(const __nv_bfloat16* __restrict__ Ah,
                                              const __nv_bfloat16* __restrict__ Al,
                                              const __nv_bfloat16* __restrict__ Bh,
                                              const __nv_bfloat16* __restrict__ Bl,
                                              int wy, int wx, int lane,
                                              float c[4][4][4])
{
    const int g = lane >> 2, t = lane & 3;
    uint32_t ah[4][4], al[4][4], bh[4][2], bl[4][2];
    #pragma unroll
    for (int i = 0; i < 4; i++){
        const int r0 = (wy*64 + i*16 + g)*P + 2*t;
        ah[i][0] = *(const uint32_t*)(Ah + r0);
        ah[i][1] = *(const uint32_t*)(Ah + r0 + 8*P);
        ah[i][2] = *(const uint32_t*)(Ah + r0 + 8);
        ah[i][3] = *(const uint32_t*)(Ah + r0 + 8*P + 8);
        al[i][0] = *(const uint32_t*)(Al + r0);
        al[i][1] = *(const uint32_t*)(Al + r0 + 8*P);
        al[i][2] = *(const uint32_t*)(Al + r0 + 8);
        al[i][3] = *(const uint32_t*)(Al + r0 + 8*P + 8);
    }
    #pragma unroll
    for (int j = 0; j < 4; j++){
        const int rb = (wx*32 + j*8 + g)*P + 2*t;
        bh[j][0] = *(const uint32_t*)(Bh + rb);
        bh[j][1] = *(const uint32_t*)(Bh + rb + 8);
        bl[j][0] = *(const uint32_t*)(Bl + rb);
        bl[j][1] = *(const uint32_t*)(Bl + rb + 8);
    }
    mma3pass(c, ah, al, bh, bl);
}

// ============================================================================
// Kernel 1: S-build.  S tile = relu(Em En^T), K=64; writes bf16 hi/lo planes
// + row-sum partials.  grid (8 mt, 8 nt, 32 g), 256 threads.
// ============================================================================
#define SB_PITCH 72
#define SB_TILE  (128*SB_PITCH)
#define SB_SMEM  (2*SB_TILE*4)          // 73728 B

__global__ void __launch_bounds__(256,2) k_sbuild(const float* __restrict__ E)
{
    extern __shared__ float sm[];
    const uint32_t smb = smem_u32(sm);
    const int tid = threadIdx.x, lane = tid & 31, wid = tid >> 5;
    const int wy = wid >> 2, wx = wid & 3;
    const int mt = blockIdx.x, nt = blockIdx.y, gb = blockIdx.z;

    const float* Emg = E + (size_t)(gb*MN + mt*128)*ED;
    const float* Eng = E + (size_t)(gb*MN + nt*128)*ED;
    // coverage: 2 tiles x 128 rows x 16 float4 = 4096 ops = 8 rounds x 256 thr x 2
    #pragma unroll
    for (int r = 0; r < 8; r++){
        int id = r*256 + tid;
        int m = id >> 4, f = id & 15;
        cpa16(smb + m*288 + f*16,               Emg + (size_t)m*ED + f*4);
        cpa16(smb + SB_TILE*4 + m*288 + f*16,   Eng + (size_t)m*ED + f*4);
    }
    CP_COMMIT(); CP_WAIT(0);
    __syncthreads();

    float c4[4][4][4] = {};
    #pragma unroll
    for (int kk = 0; kk < 64; kk += 16)
        mma_step_f32<SB_PITCH, SB_PITCH>(sm, sm + SB_TILE, kk, wy, wx, lane, c4);

    const int g = lane >> 2, t = lane & 3;
    const int rowbase = gb*MN + mt*128;
    #pragma unroll
    for (int i = 0; i < 4; i++){
        #pragma unroll
        for (int h = 0; h < 2; h++){
            const int row = rowbase + wy*64 + i*16 + g + h*8;
            const size_t soff = (size_t)row*MN + nt*128;
            float rsum = 0.f;
            #pragma unroll
            for (int j = 0; j < 4; j++){
                float v0 = fmaxf(c4[i][j][h*2+0], 0.f);
                float v1 = fmaxf(c4[i][j][h*2+1], 0.f);
                rsum += v0 + v1;
                uint32_t h01, l01;
                bsplit2(v0, v1, h01, l01);
                const size_t o = soff + wx*32 + j*8 + 2*t;
                *(uint32_t*)&g_Sh[o] = h01;
                *(uint32_t*)&g_Sl[o] = l01;
            }
            rsum += __shfl_xor_sync(0xFFFFFFFFu, rsum, 1);
            rsum += __shfl_xor_sync(0xFFFFFFFFu, rsum, 2);
            if (t == 0) g_degp[row*32 + nt*4 + wx] = rsum;
        }
    }
}

// ============================================================================
// Kernel 2: dinv = rsqrt(1 + sum of 32 partials)
// ============================================================================
__global__ void k_dinv()
{
    const int i = blockIdx.x*256 + threadIdx.x;
    float s = 1.0f;
    #pragma unroll
    for (int j = 0; j < 32; j++) s += g_degp[i*32 + j];
    g_dinv[i] = rsqrtf(s);
}

// ============================================================================
// Kernel 3: Z = dinv ⊙ (In @ W^T).  K=128, 4 chunks, double-buffered.
// Writes g_z fp32 + transposed bf16 split planes.  grid 256, 256 threads.
// ============================================================================
#define GW_PITCH 40
#define GW_TILE  (128*GW_PITCH)
#define GW_STAGE (2*GW_TILE)
#define GW_SMEM  (2*GW_STAGE*4)         // 81920 B

__global__ void __launch_bounds__(256,2) k_gemmw(const float* __restrict__ xin,
                                                 const float* __restrict__ W,
                                                 int use_internal)
{
    extern __shared__ float sm[];
    const uint32_t smb = smem_u32(sm);
    const float* __restrict__ in = use_internal ? g_y : xin;
    const int tid = threadIdx.x, lane = tid & 31, wid = tid >> 5;
    const int wy = wid >> 2, wx = wid & 3;
    const int rbase = blockIdx.x*128;

    auto copy = [&](int c){
        const uint32_t ab = smb + (uint32_t)(c & 1)*GW_STAGE*4;
        const uint32_t bb = ab + GW_TILE*4;
        // coverage: 2 tiles x 128 rows x 8 float4 = 2048 ops = 4 rounds x 256 x 2
        #pragma unroll
        for (int r = 0; r < 4; r++){
            int id = r*256 + tid;
            int m = id >> 3, f = id & 7;
            cpa16(ab + m*160 + f*16, in + (size_t)(rbase + m)*128 + c*32 + f*4);
            cpa16(bb + m*160 + f*16, W  + (size_t)m*128          + c*32 + f*4);
        }
        CP_COMMIT();
    };

    float c4[4][4][4] = {};
    copy(0);
    for (int c = 0; c < 4; c++){
        if (c < 3){ copy(c + 1); CP_WAIT(1); } else { CP_WAIT(0); }
        __syncthreads();
        const float* As = sm + (c & 1)*GW_STAGE;
        const float* Bs = As + GW_TILE;
        #pragma unroll
        for (int kk = 0; kk < 32; kk += 16)
            mma_step_f32<GW_PITCH, GW_PITCH>(As, Bs, kk, wy, wx, lane, c4);
        __syncthreads();
    }

    const int g = lane >> 2, t = lane & 3;
    #pragma unroll
    for (int i = 0; i < 4; i++){
        #pragma unroll
        for (int h = 0; h < 2; h++){
            const int row = rbase + wy*64 + i*16 + g + h*8;
            const float sc = g_dinv[row];
            const int gb = row >> 10, nloc = row & 1023;
            float* zr = g_z + (size_t)row*128;
            #pragma unroll
            for (int j = 0; j < 4; j++){
                const int col = wx*32 + j*8 + 2*t;
                float v0 = sc*c4[i][j][h*2], v1 = sc*c4[i][j][h*2+1];
                *(float2*)&zr[col] = make_float2(v0, v1);
                __nv_bfloat16 h0 = __float2bfloat16(v0);
                __nv_bfloat16 h1 = __float2bfloat16(v1);
                const size_t o0 = ((size_t)gb*DF + col    )*MN + nloc;
                const size_t o1 = ((size_t)gb*DF + col + 1)*MN + nloc;
                g_zth[o0] = h0;  g_ztl[o0] = __float2bfloat16(v0 - __bfloat162float(h0));
                g_zth[o1] = h1;  g_ztl[o1] = __float2bfloat16(v1 - __bfloat162float(h1));
            }
        }
    }
}

// ============================================================================
// Kernel 4: propagation.  out = relu(dinv_m ⊙ (S@Z + Z_m)).  K=1024.
// 64 chunks of k16, 4-stage cp.async pipeline, all-bf16 pre-split tiles.
// grid (8 mt, 32 g), 256 threads.
// ============================================================================
#define PR_PITCH 24                         // bf16 elems; 48 B rows
#define PR_PLANE (128*PR_PITCH)             // 3072 bf16 = 6144 B
#define PR_STAGE (4*PR_PLANE)               // Sh, Sl, Zth, Ztl = 24576 B
#define PR_NSTG  4
#define PR_SMEM  (PR_NSTG*PR_STAGE*2)       // 98304 B

__global__ void __launch_bounds__(256,2) k_prop(float* __restrict__ outext, int to_internal)
{
    extern __shared__ __nv_bfloat16 smh[];
    const uint32_t smb = smem_u32(smh);
    const int tid = threadIdx.x, lane = tid & 31, wid = tid >> 5;
    const int wy = wid >> 2, wx = wid & 3;
    const int mt = blockIdx.x, gb = blockIdx.y;
    float* __restrict__ dst = to_internal ? g_y : outext;

    const int mrow0 = gb*MN + mt*128;

    // stage copy coverage: 4 planes x 128 rows x 2 ops = 1024 = 4 rounds x 256 thr
    auto copy = [&](int c){
        const uint32_t sb = smb + (uint32_t)(c & (PR_NSTG-1))*PR_STAGE*2;
        #pragma unroll
        for (int r = 0; r < 4; r++){
            int id = r*256 + tid;              // id in [0, 1024)
            int plane = id >> 8, rem = id & 255;
            int row = rem >> 1, f = rem & 1;
            const uint32_t dsta = sb + plane*(PR_PLANE*2) + row*48 + f*16;
            const __nv_bfloat16* src;
            if      (plane == 0) src = g_Sh  + (size_t)(mrow0 + row)*MN + c*16 + f*8;
            else if (plane == 1) src = g_Sl  + (size_t)(mrow0 + row)*MN + c*16 + f*8;
            else if (plane == 2) src = g_zth + ((size_t)gb*DF + row)*MN + c*16 + f*8;
            else                 src = g_ztl + ((size_t)gb*DF + row)*MN + c*16 + f*8;
            cpa16(dsta, src);
        }
        CP_COMMIT();
    };

    float c4[4][4][4] = {};
    copy(0); copy(1); copy(2);
    #pragma unroll 4
    for (int c = 0; c < 64; c++){
        if (c + 3 < 64) { copy(c + 3); CP_WAIT(3); }
        else if (c == 61) CP_WAIT(2);
        else if (c == 62) CP_WAIT(1);
        else              CP_WAIT(0);
        __syncthreads();
        const __nv_bfloat16* Ah = smh + (size_t)(c & (PR_NSTG-1))*PR_STAGE;
        const __nv_bfloat16* Al = Ah + PR_PLANE;
        const __nv_bfloat16* Bh = Ah + 2*PR_PLANE;
        const __nv_bfloat16* Bl = Ah + 3*PR_PLANE;
        mma_step_bf16<PR_PITCH>(Ah, Al, Bh, Bl, wy, wx, lane, c4);
        __syncthreads();
    }

    const int g = lane >> 2, t = lane & 3;
    #pragma unroll
    for (int i = 0; i < 4; i++){
        #pragma unroll
        for (int h = 0; h < 2; h++){
            const int row = mrow0 + wy*64 + i*16 + g + h*8;
            const float sc = g_dinv[row];
            const float* zr = g_z + (size_t)row*128;
            float* orow = dst + (size_t)row*128;
            #pragma unroll
            for (int j = 0; j < 4; j++){
                const int col = wx*32 + j*8 + 2*t;
                float2 z = *(const float2*)&zr[col];
                float2 o;
                o.x = fmaxf(sc*(c4[i][j][h*2]   + z.x), 0.f);
                o.y = fmaxf(sc*(c4[i][j][h*2+1] + z.y), 0.f);
                *(float2*)&orow[col] = o;
            }
        }
    }
}

// ============================================================================
extern "C" void kernel_launch(void* const* d_in, const int* in_sizes, int n_in,
                              void* d_out, int out_size)
{
    (void)in_sizes; (void)n_in; (void)out_size;
    const float* X  = (const float*)d_in[0];
    const float* E  = (const float*)d_in[1];
    const float* W1 = (const float*)d_in[2];
    const float* W2 = (const float*)d_in[3];
    float* out = (float*)d_out;

    cudaFuncSetAttribute(k_sbuild, cudaFuncAttributeMaxDynamicSharedMemorySize, SB_SMEM);
    cudaFuncSetAttribute(k_gemmw,  cudaFuncAttributeMaxDynamicSharedMemorySize, GW_SMEM);
    cudaFuncSetAttribute(k_prop,   cudaFuncAttributeMaxDynamicSharedMemorySize, PR_SMEM);

    k_sbuild<<<dim3(8, 8, 32), 256, SB_SMEM>>>(E);
    k_dinv  <<<NROWS/256, 256>>>();
    k_gemmw <<<256, 256, GW_SMEM>>>(X, W1, 0);
    k_prop  <<<dim3(8, 32), 256, PR_SMEM>>>(nullptr, 1);
    k_gemmw <<<256, 256, GW_SMEM>>>(nullptr, W2, 1);
    k_prop  <<<dim3(8, 32), 256, PR_SMEM>>>(out, 0);
}

// round 9
// speedup vs baseline: 1.0749x; 1.0749x over previous
#include <cuda_runtime.h>
#include <cuda_bf16.h>
#include <cstdint>

#define BATCH 32
#define MN    1024
#define DF    128
#define ED    64
#define NROWS (BATCH*MN)   // 32768

// ---------------- device scratch (no runtime allocation allowed) ----------------
__device__ __nv_bfloat16 g_Sh[(size_t)BATCH*MN*MN];   // 64 MB: hi plane of S
__device__ __nv_bfloat16 g_Sl[(size_t)BATCH*MN*MN];   // 64 MB: lo plane of S
__device__ float         g_degp[NROWS*4];             // row-sum partials (wx)
__device__ float         g_dinv[NROWS];
__device__ float         g_z  [(size_t)NROWS*DF];     // Z fp32 row-major (identity term)
__device__ __nv_bfloat16 g_zth[(size_t)BATCH*DF*MN];  // Z^T hi plane [g][d][n]
__device__ __nv_bfloat16 g_ztl[(size_t)BATCH*DF*MN];  // Z^T lo plane
__device__ float         g_y  [(size_t)NROWS*DF];     // layer-1 output fp32

// ---------------- helpers ----------------
__device__ __forceinline__ uint32_t smem_u32(const void* p){
    uint32_t a;
    asm("{ .reg .u64 t; cvta.to.shared.u64 t, %1; cvt.u32.u64 %0, t; }" : "=r"(a) : "l"(p));
    return a;
}
__device__ __forceinline__ void cpa16(uint32_t d, const void* s){
    asm volatile("cp.async.cg.shared.global [%0], [%1], 16;" :: "r"(d), "l"(s));
}
#define CP_COMMIT() asm volatile("cp.async.commit_group;" ::: "memory")
#define CP_WAIT(n)  asm volatile("cp.async.wait_group %0;" :: "n"(n) : "memory")

// bf16 2-term split of a pair (v0 -> low half, v1 -> high half of each packed reg).
__device__ __forceinline__ void bsplit2(float v0, float v1, uint32_t& h01, uint32_t& l01){
    asm("cvt.rn.bf16x2.f32 %0, %1, %2;" : "=r"(h01) : "f"(v1), "f"(v0));
    float h0 = __uint_as_float(h01 << 16);
    float h1 = __uint_as_float(h01 & 0xFFFF0000u);
    float l0 = v0 - h0, l1 = v1 - h1;
    asm("cvt.rn.bf16x2.f32 %0, %1, %2;" : "=r"(l01) : "f"(l1), "f"(l0));
}

__device__ __forceinline__ void mma16(float c[4], const uint32_t a[4], const uint32_t b[2]){
    asm volatile(
        "mma.sync.aligned.m16n8k16.row.col.f32.bf16.bf16.f32 "
        "{%0,%1,%2,%3}, {%4,%5,%6,%7}, {%8,%9}, {%0,%1,%2,%3};"
        : "+f"(c[0]), "+f"(c[1]), "+f"(c[2]), "+f"(c[3])
        : "r"(a[0]), "r"(a[1]), "r"(a[2]), "r"(a[3]), "r"(b[0]), "r"(b[1]));
}

__device__ __forceinline__ void mma3pass(float c[4][4][4],
    const uint32_t ah[4][4], const uint32_t al[4][4],
    const uint32_t bh[4][2], const uint32_t bl[4][2])
{
    #pragma unroll
    for (int j = 0; j < 4; j++)
        #pragma unroll
        for (int i = 0; i < 4; i++) mma16(c[i][j], ah[i], bh[j]);
    #pragma unroll
    for (int j = 0; j < 4; j++)
        #pragma unroll
        for (int i = 0; i < 4; i++) mma16(c[i][j], al[i], bh[j]);
    #pragma unroll
    for (int j = 0; j < 4; j++)
        #pragma unroll
        for (int i = 0; i < 4; i++) mma16(c[i][j], ah[i], bl[j]);
}

// One k16 step from fp32 smem tiles (A [m][k] pitch PA, B [n][k] pitch PB).
template<int PA, int PB>
__device__ __forceinline__ void mma_step_f32(const float* __restrict__ As,
                                             const float* __restrict__ Bs,
                                             int kk, int wy, int wx, int lane,
                                             float c[4][4][4])
{
    const int g = lane >> 2, t = lane & 3;
    uint32_t ah[4][4], al[4][4], bh[4][2], bl[4][2];
    #pragma unroll
    for (int i = 0; i < 4; i++){
        const float* ap = As + (wy*64 + i*16 + g)*PA + kk + 2*t;
        float2 v;
        v = *(const float2*)(ap);            bsplit2(v.x, v.y, ah[i][0], al[i][0]);
        v = *(const float2*)(ap + 8*PA);     bsplit2(v.x, v.y, ah[i][1], al[i][1]);
        v = *(const float2*)(ap + 8);        bsplit2(v.x, v.y, ah[i][2], al[i][2]);
        v = *(const float2*)(ap + 8*PA + 8); bsplit2(v.x, v.y, ah[i][3], al[i][3]);
    }
    #pragma unroll
    for (int j = 0; j < 4; j++){
        const float* bp = Bs + (wx*32 + j*8 + g)*PB + kk + 2*t;
        float2 v;
        v = *(const float2*)(bp);     bsplit2(v.x, v.y, bh[j][0], bl[j][0]);
        v = *(const float2*)(bp + 8); bsplit2(v.x, v.y, bh[j][1], bl[j][1]);
    }
    mma3pass(c, ah, al, bh, bl);
}

// One k16 step from pre-split bf16 planes, pitch P elems (P=40: conflict-free).
template<int P>
__device__ __forceinline__ void mma_step_bf16(const __nv_bfloat16* __restrict__ Ah,
                                              const __nv_bfloat16* __restrict__ Al,
                                              const __nv_bfloat16* __restrict__ Bh,
                                              const __nv_bfloat16* __restrict__ Bl,
                                              int kk, int wy, int wx, int lane,
                                              float c[4][4][4])
{
    const int g = lane >> 2, t = lane & 3;
    uint32_t ah[4][4], al[4][4], bh[4][2], bl[4][2];
    #pragma unroll
    for (int i = 0; i < 4; i++){
        const int r0 = (wy*64 + i*16 + g)*P + kk + 2*t;
        ah[i][0] = *(const uint32_t*)(Ah + r0);
        ah[i][1] = *(const uint32_t*)(Ah + r0 + 8*P);
        ah[i][2] = *(const uint32_t*)(Ah + r0 + 8);
        ah[i][3] = *(const uint32_t*)(Ah + r0 + 8*P + 8);
        al[i][0] = *(const uint32_t*)(Al + r0);
        al[i][1] = *(const uint32_t*)(Al + r0 + 8*P);
        al[i][2] = *(const uint32_t*)(Al + r0 + 8);
        al[i][3] = *(const uint32_t*)(Al + r0 + 8*P + 8);
    }
    #pragma unroll
    for (int j = 0; j < 4; j++){
        const int rb = (wx*32 + j*8 + g)*P + kk + 2*t;
        bh[j][0] = *(const uint32_t*)(Bh + rb);
        bh[j][1] = *(const uint32_t*)(Bh + rb + 8);
        bl[j][0] = *(const uint32_t*)(Bl + rb);
        bl[j][1] = *(const uint32_t*)(Bl + rb + 8);
    }
    mma3pass(c, ah, al, bh, bl);
}

// ============================================================================
// Kernel 1: S-build v2.  Per CTA: one mt row x ALL 8 nt tiles, Em loaded once,
// En double-buffered (prefetch distance 2).  grid (8 mt, 32 g), 256 threads.
// ============================================================================
#define SB_PITCH 72
#define SB_TILE  (128*SB_PITCH)              // floats (36864 B)
#define SB_SMEM  (3*SB_TILE*4)               // Em + 2 En stages = 110592 B

__global__ void __launch_bounds__(256,2) k_sbuild(const float* __restrict__ E)
{
    extern __shared__ float sm[];
    const uint32_t smb = smem_u32(sm);
    const int tid = threadIdx.x, lane = tid & 31, wid = tid >> 5;
    const int wy = wid >> 2, wx = wid & 3;
    const int mt = blockIdx.x, gb = blockIdx.y;

    const float* Emg = E + (size_t)(gb*MN + mt*128)*ED;
    const float* Eg  = E + (size_t)gb*MN*ED;

    // coverage per tile: 128 rows x 16 float4 = 2048 ops = 8 rounds x 256 thr
    auto copy_en = [&](int nt){
        const uint32_t base = smb + (uint32_t)(1 + (nt & 1))*SB_TILE*4;
        const float* src = Eg + (size_t)(nt*128)*ED;
        #pragma unroll
        for (int r = 0; r < 8; r++){
            int id = r*256 + tid;
            int m = id >> 4, f = id & 15;
            cpa16(base + m*288 + f*16, src + (size_t)m*ED + f*4);
        }
        CP_COMMIT();
    };

    // group 0: Em + En(0)
    #pragma unroll
    for (int r = 0; r < 8; r++){
        int id = r*256 + tid;
        int m = id >> 4, f = id & 15;
        cpa16(smb + m*288 + f*16, Emg + (size_t)m*ED + f*4);
    }
    {   // En(0) into stage 0 (same group as Em)
        const float* src = Eg;
        #pragma unroll
        for (int r = 0; r < 8; r++){
            int id = r*256 + tid;
            int m = id >> 4, f = id & 15;
            cpa16(smb + SB_TILE*4 + m*288 + f*16, src + (size_t)m*ED + f*4);
        }
    }
    CP_COMMIT();
    copy_en(1);   // group 1

    const int g = lane >> 2, t = lane & 3;
    const int rowbase = gb*MN + mt*128;
    float rsum_acc[4][2] = {};

    for (int nt = 0; nt < 8; nt++){
        if (nt < 7) { CP_WAIT(1); } else { CP_WAIT(0); }
        __syncthreads();

        const float* En = sm + (1 + (nt & 1))*SB_TILE;
        float c4[4][4][4] = {};
        #pragma unroll
        for (int kk = 0; kk < 64; kk += 16)
            mma_step_f32<SB_PITCH, SB_PITCH>(sm, En, kk, wy, wx, lane, c4);
        __syncthreads();            // all warps done reading stage (nt&1)

        if (nt + 2 <= 7) copy_en(nt + 2);   // prefetch into freed stage

        // epilogue: relu, split-store S planes, accumulate row sums
        #pragma unroll
        for (int i = 0; i < 4; i++){
            #pragma unroll
            for (int h = 0; h < 2; h++){
                const int row = rowbase + wy*64 + i*16 + g + h*8;
                const size_t soff = (size_t)row*MN + nt*128;
                float rsum = 0.f;
                #pragma unroll
                for (int j = 0; j < 4; j++){
                    float v0 = fmaxf(c4[i][j][h*2+0], 0.f);
                    float v1 = fmaxf(c4[i][j][h*2+1], 0.f);
                    rsum += v0 + v1;
                    uint32_t h01, l01;
                    bsplit2(v0, v1, h01, l01);
                    const size_t o = soff + wx*32 + j*8 + 2*t;
                    *(uint32_t*)&g_Sh[o] = h01;
                    *(uint32_t*)&g_Sl[o] = l01;
                }
                rsum_acc[i][h] += rsum;
            }
        }
    }

    // reduce row sums (over t within quad) and store one partial per (row, wx)
    #pragma unroll
    for (int i = 0; i < 4; i++){
        #pragma unroll
        for (int h = 0; h < 2; h++){
            float rsum = rsum_acc[i][h];
            rsum += __shfl_xor_sync(0xFFFFFFFFu, rsum, 1);
            rsum += __shfl_xor_sync(0xFFFFFFFFu, rsum, 2);
            if (t == 0){
                const int row = rowbase + wy*64 + i*16 + g + h*8;
                g_degp[row*4 + wx] = rsum;
            }
        }
    }
}

// ============================================================================
// Kernel 2: dinv = rsqrt(1 + sum of 4 partials)
// ============================================================================
__global__ void k_dinv()
{
    const int i = blockIdx.x*256 + threadIdx.x;
    float s = 1.0f;
    #pragma unroll
    for (int j = 0; j < 4; j++) s += g_degp[i*4 + j];
    g_dinv[i] = rsqrtf(s);
}

// ============================================================================
// Kernel 3: Z = dinv ⊙ (In @ W^T).  K=128, 4 chunks, double-buffered.
// Writes g_z fp32 + transposed bf16 split planes.  grid 256, 256 threads.
// ============================================================================
#define GW_PITCH 40
#define GW_TILE  (128*GW_PITCH)
#define GW_STAGE (2*GW_TILE)
#define GW_SMEM  (2*GW_STAGE*4)         // 81920 B

__global__ void __launch_bounds__(256,2) k_gemmw(const float* __restrict__ xin,
                                                 const float* __restrict__ W,
                                                 int use_internal)
{
    extern __shared__ float sm[];
    const uint32_t smb = smem_u32(sm);
    const float* __restrict__ in = use_internal ? g_y : xin;
    const int tid = threadIdx.x, lane = tid & 31, wid = tid >> 5;
    const int wy = wid >> 2, wx = wid & 3;
    const int rbase = blockIdx.x*128;

    auto copy = [&](int c){
        const uint32_t ab = smb + (uint32_t)(c & 1)*GW_STAGE*4;
        const uint32_t bb = ab + GW_TILE*4;
        // coverage: 2 tiles x 128 rows x 8 float4 = 2048 ops = 4 rounds x 256 x 2
        #pragma unroll
        for (int r = 0; r < 4; r++){
            int id = r*256 + tid;
            int m = id >> 3, f = id & 7;
            cpa16(ab + m*160 + f*16, in + (size_t)(rbase + m)*128 + c*32 + f*4);
            cpa16(bb + m*160 + f*16, W  + (size_t)m*128          + c*32 + f*4);
        }
        CP_COMMIT();
    };

    float c4[4][4][4] = {};
    copy(0);
    for (int c = 0; c < 4; c++){
        if (c < 3){ copy(c + 1); CP_WAIT(1); } else { CP_WAIT(0); }
        __syncthreads();
        const float* As = sm + (c & 1)*GW_STAGE;
        const float* Bs = As + GW_TILE;
        #pragma unroll
        for (int kk = 0; kk < 32; kk += 16)
            mma_step_f32<GW_PITCH, GW_PITCH>(As, Bs, kk, wy, wx, lane, c4);
        __syncthreads();
    }

    const int g = lane >> 2, t = lane & 3;
    #pragma unroll
    for (int i = 0; i < 4; i++){
        #pragma unroll
        for (int h = 0; h < 2; h++){
            const int row = rbase + wy*64 + i*16 + g + h*8;
            const float sc = g_dinv[row];
            const int gb = row >> 10, nloc = row & 1023;
            float* zr = g_z + (size_t)row*128;
            #pragma unroll
            for (int j = 0; j < 4; j++){
                const int col = wx*32 + j*8 + 2*t;
                float v0 = sc*c4[i][j][h*2], v1 = sc*c4[i][j][h*2+1];
                *(float2*)&zr[col] = make_float2(v0, v1);
                __nv_bfloat16 h0 = __float2bfloat16(v0);
                __nv_bfloat16 h1 = __float2bfloat16(v1);
                const size_t o0 = ((size_t)gb*DF + col    )*MN + nloc;
                const size_t o1 = ((size_t)gb*DF + col + 1)*MN + nloc;
                g_zth[o0] = h0;  g_ztl[o0] = __float2bfloat16(v0 - __bfloat162float(h0));
                g_zth[o1] = h1;  g_ztl[o1] = __float2bfloat16(v1 - __bfloat162float(h1));
            }
        }
    }
}

// ============================================================================
// Kernel 4: propagation (round-6 proven config).  out = relu(dinv⊙(S@Z + Z)).
// K=1024: 32 chunks of k32, 2-stage cp.async, all-bf16 pre-split tiles.
// grid (8 mt, 32 g), 256 threads.
// ============================================================================
#define PR_PITCH 40                     // bf16 elems; 80 B rows, conflict-free
#define PR_PLANE (128*PR_PITCH)         // 5120 bf16 = 10240 B
#define PR_STAGE (4*PR_PLANE)           // Sh, Sl, Zth, Ztl
#define PR_SMEM  (2*PR_STAGE*2)         // 81920 B

__global__ void __launch_bounds__(256,2) k_prop(float* __restrict__ outext, int to_internal)
{
    extern __shared__ __nv_bfloat16 smh[];
    const uint32_t smb = smem_u32(smh);
    const int tid = threadIdx.x, lane = tid & 31, wid = tid >> 5;
    const int wy = wid >> 2, wx = wid & 3;
    const int mt = blockIdx.x, gb = blockIdx.y;
    float* __restrict__ dst = to_internal ? g_y : outext;

    const int mrow0 = gb*MN + mt*128;

    // coverage: 4 planes x 128 rows x 4 ops = 2048 = 8 rounds x 256 thr
    auto copy = [&](int c){
        const uint32_t sb = smb + (uint32_t)(c & 1)*PR_STAGE*2;
        #pragma unroll
        for (int r = 0; r < 8; r++){
            int id = r*256 + tid;
            int plane = id >> 9, rem = id & 511;
            int row = rem >> 2, f = rem & 3;
            const uint32_t dsta = sb + plane*(PR_PLANE*2) + row*80 + f*16;
            const __nv_bfloat16* src;
            if      (plane == 0) src = g_Sh  + (size_t)(mrow0 + row)*MN + c*32 + f*8;
            else if (plane == 1) src = g_Sl  + (size_t)(mrow0 + row)*MN + c*32 + f*8;
            else if (plane == 2) src = g_zth + ((size_t)gb*DF + row)*MN + c*32 + f*8;
            else                 src = g_ztl + ((size_t)gb*DF + row)*MN + c*32 + f*8;
            cpa16(dsta, src);
        }
        CP_COMMIT();
    };

    float c4[4][4][4] = {};
    copy(0);
    for (int c = 0; c < 32; c++){
        if (c < 31){ copy(c + 1); CP_WAIT(1); } else { CP_WAIT(0); }
        __syncthreads();
        const __nv_bfloat16* Ah = smh + (size_t)(c & 1)*PR_STAGE;
        const __nv_bfloat16* Al = Ah + PR_PLANE;
        const __nv_bfloat16* Bh = Ah + 2*PR_PLANE;
        const __nv_bfloat16* Bl = Ah + 3*PR_PLANE;
        #pragma unroll
        for (int kk = 0; kk < 32; kk += 16)
            mma_step_bf16<PR_PITCH>(Ah, Al, Bh, Bl, kk, wy, wx, lane, c4);
        __syncthreads();
    }

    const int g = lane >> 2, t = lane & 3;
    #pragma unroll
    for (int i = 0; i < 4; i++){
        #pragma unroll
        for (int h = 0; h < 2; h++){
            const int row = mrow0 + wy*64 + i*16 + g + h*8;
            const float sc = g_dinv[row];
            const float* zr = g_z + (size_t)row*128;
            float* orow = dst + (size_t)row*128;
            #pragma unroll
            for (int j = 0; j < 4; j++){
                const int col = wx*32 + j*8 + 2*t;
                float2 z = *(const float2*)&zr[col];
                float2 o;
                o.x = fmaxf(sc*(c4[i][j][h*2]   + z.x), 0.f);
                o.y = fmaxf(sc*(c4[i][j][h*2+1] + z.y), 0.f);
                *(float2*)&orow[col] = o;
            }
        }
    }
}

// ============================================================================
extern "C" void kernel_launch(void* const* d_in, const int* in_sizes, int n_in,
                              void* d_out, int out_size)
{
    (void)in_sizes; (void)n_in; (void)out_size;
    const float* X  = (const float*)d_in[0];
    const float* E  = (const float*)d_in[1];
    const float* W1 = (const float*)d_in[2];
    const float* W2 = (const float*)d_in[3];
    float* out = (float*)d_out;

    cudaFuncSetAttribute(k_sbuild, cudaFuncAttributeMaxDynamicSharedMemorySize, SB_SMEM);
    cudaFuncSetAttribute(k_gemmw,  cudaFuncAttributeMaxDynamicSharedMemorySize, GW_SMEM);
    cudaFuncSetAttribute(k_prop,   cudaFuncAttributeMaxDynamicSharedMemorySize, PR_SMEM);

    k_sbuild<<<dim3(8, 32), 256, SB_SMEM>>>(E);
    k_dinv  <<<NROWS/256, 256>>>();
    k_gemmw <<<256, 256, GW_SMEM>>>(X, W1, 0);
    k_prop  <<<dim3(8, 32), 256, PR_SMEM>>>(nullptr, 1);
    k_gemmw <<<256, 256, GW_SMEM>>>(nullptr, W2, 1);
    k_prop  <<<dim3(8, 32), 256, PR_SMEM>>>(out, 0);
}

// round 11
// speedup vs baseline: 1.1304x; 1.0516x over previous
#include <cuda_runtime.h>
#include <cuda_bf16.h>
#include <cstdint>

#define BATCH 32
#define MN    1024
#define DF    128
#define ED    64
#define NROWS (BATCH*MN)   // 32768

// ---------------- device scratch (no runtime allocation allowed) ----------------
__device__ __align__(16) __nv_bfloat16 g_Eh[(size_t)NROWS*ED];      // 4 MB
__device__ __align__(16) __nv_bfloat16 g_El[(size_t)NROWS*ED];      // 4 MB
__device__ __align__(16) __nv_bfloat16 g_Sh[(size_t)BATCH*MN*MN];   // 64 MB
__device__ __align__(16) __nv_bfloat16 g_Sl[(size_t)BATCH*MN*MN];   // 64 MB
__device__ float         g_degp[NROWS*4];
__device__ float         g_dinv[NROWS];
__device__ float         g_z  [(size_t)NROWS*DF];
__device__ __align__(16) __nv_bfloat16 g_zth[(size_t)BATCH*DF*MN];  // Z^T hi [g][d][n]
__device__ __align__(16) __nv_bfloat16 g_ztl[(size_t)BATCH*DF*MN];  // Z^T lo
__device__ float         g_y  [(size_t)NROWS*DF];

// ---------------- helpers ----------------
__device__ __forceinline__ uint32_t smem_u32(const void* p){
    uint32_t a;
    asm("{ .reg .u64 t; cvta.to.shared.u64 t, %1; cvt.u32.u64 %0, t; }" : "=r"(a) : "l"(p));
    return a;
}
__device__ __forceinline__ void cpa16(uint32_t d, const void* s){
    asm volatile("cp.async.cg.shared.global [%0], [%1], 16;" :: "r"(d), "l"(s));
}
#define CP_COMMIT() asm volatile("cp.async.commit_group;" ::: "memory")
#define CP_WAIT(n)  asm volatile("cp.async.wait_group %0;" :: "n"(n) : "memory")

// bf16 2-term split of a pair (v0 -> low half, v1 -> high half of packed reg).
__device__ __forceinline__ void bsplit2(float v0, float v1, uint32_t& h01, uint32_t& l01){
    asm("cvt.rn.bf16x2.f32 %0, %1, %2;" : "=r"(h01) : "f"(v1), "f"(v0));
    float h0 = __uint_as_float(h01 << 16);
    float h1 = __uint_as_float(h01 & 0xFFFF0000u);
    float l0 = v0 - h0, l1 = v1 - h1;
    asm("cvt.rn.bf16x2.f32 %0, %1, %2;" : "=r"(l01) : "f"(l1), "f"(l0));
}

__device__ __forceinline__ void mma16(float c[4], const uint32_t a[4], const uint32_t b[2]){
    asm volatile(
        "mma.sync.aligned.m16n8k16.row.col.f32.bf16.bf16.f32 "
        "{%0,%1,%2,%3}, {%4,%5,%6,%7}, {%8,%9}, {%0,%1,%2,%3};"
        : "+f"(c[0]), "+f"(c[1]), "+f"(c[2]), "+f"(c[3])
        : "r"(a[0]), "r"(a[1]), "r"(a[2]), "r"(a[3]), "r"(b[0]), "r"(b[1]));
}

__device__ __forceinline__ void mma3pass(float c[4][4][4],
    const uint32_t ah[4][4], const uint32_t al[4][4],
    const uint32_t bh[4][2], const uint32_t bl[4][2])
{
    #pragma unroll
    for (int j = 0; j < 4; j++)
        #pragma unroll
        for (int i = 0; i < 4; i++) mma16(c[i][j], ah[i], bh[j]);
    #pragma unroll
    for (int j = 0; j < 4; j++)
        #pragma unroll
        for (int i = 0; i < 4; i++) mma16(c[i][j], al[i], bh[j]);
    #pragma unroll
    for (int j = 0; j < 4; j++)
        #pragma unroll
        for (int i = 0; i < 4; i++) mma16(c[i][j], ah[i], bl[j]);
}

// One k16 step from fp32 smem tiles (A [m][k] pitch PA, B [n][k] pitch PB).
template<int PA, int PB>
__device__ __forceinline__ void mma_step_f32(const float* __restrict__ As,
                                             const float* __restrict__ Bs,
                                             int kk, int wy, int wx, int lane,
                                             float c[4][4][4])
{
    const int g = lane >> 2, t = lane & 3;
    uint32_t ah[4][4], al[4][4], bh[4][2], bl[4][2];
    #pragma unroll
    for (int i = 0; i < 4; i++){
        const float* ap = As + (wy*64 + i*16 + g)*PA + kk + 2*t;
        float2 v;
        v = *(const float2*)(ap);            bsplit2(v.x, v.y, ah[i][0], al[i][0]);
        v = *(const float2*)(ap + 8*PA);     bsplit2(v.x, v.y, ah[i][1], al[i][1]);
        v = *(const float2*)(ap + 8);        bsplit2(v.x, v.y, ah[i][2], al[i][2]);
        v = *(const float2*)(ap + 8*PA + 8); bsplit2(v.x, v.y, ah[i][3], al[i][3]);
    }
    #pragma unroll
    for (int j = 0; j < 4; j++){
        const float* bp = Bs + (wx*32 + j*8 + g)*PB + kk + 2*t;
        float2 v;
        v = *(const float2*)(bp);     bsplit2(v.x, v.y, bh[j][0], bl[j][0]);
        v = *(const float2*)(bp + 8); bsplit2(v.x, v.y, bh[j][1], bl[j][1]);
    }
    mma3pass(c, ah, al, bh, bl);
}

// One k16 step from pre-split bf16 planes (A [m][k], B [n][k]; pitch P elems).
// Al/Bl may be Ah+32/Bh+32 (interleaved rows) or separate planes.
template<int P>
__device__ __forceinline__ void mma_step_bf16(const __nv_bfloat16* __restrict__ Ah,
                                              const __nv_bfloat16* __restrict__ Al,
                                              const __nv_bfloat16* __restrict__ Bh,
                                              const __nv_bfloat16* __restrict__ Bl,
                                              int kk, int wy, int wx, int lane,
                                              float c[4][4][4])
{
    const int g = lane >> 2, t = lane & 3;
    uint32_t ah[4][4], al[4][4], bh[4][2], bl[4][2];
    #pragma unroll
    for (int i = 0; i < 4; i++){
        const int r0 = (wy*64 + i*16 + g)*P + kk + 2*t;
        ah[i][0] = *(const uint32_t*)(Ah + r0);
        ah[i][1] = *(const uint32_t*)(Ah + r0 + 8*P);
        ah[i][2] = *(const uint32_t*)(Ah + r0 + 8);
        ah[i][3] = *(const uint32_t*)(Ah + r0 + 8*P + 8);
        al[i][0] = *(const uint32_t*)(Al + r0);
        al[i][1] = *(const uint32_t*)(Al + r0 + 8*P);
        al[i][2] = *(const uint32_t*)(Al + r0 + 8);
        al[i][3] = *(const uint32_t*)(Al + r0 + 8*P + 8);
    }
    #pragma unroll
    for (int j = 0; j < 4; j++){
        const int rb = (wx*32 + j*8 + g)*P + kk + 2*t;
        bh[j][0] = *(const uint32_t*)(Bh + rb);
        bh[j][1] = *(const uint32_t*)(Bh + rb + 8);
        bl[j][0] = *(const uint32_t*)(Bl + rb);
        bl[j][1] = *(const uint32_t*)(Bl + rb + 8);
    }
    mma3pass(c, ah, al, bh, bl);
}

// ============================================================================
// Kernel 0: split E into bf16 hi/lo planes.
// ============================================================================
__global__ void k_esplit(const float* __restrict__ E)
{
    const int id = blockIdx.x*256 + threadIdx.x;      // 524288 float4 total
    float4 v = *(const float4*)(E + (size_t)id*4);
    uint32_t h01, l01, h23, l23;
    bsplit2(v.x, v.y, h01, l01);
    bsplit2(v.z, v.w, h23, l23);
    *(uint2*)&g_Eh[(size_t)id*4] = make_uint2(h01, h23);
    *(uint2*)&g_El[(size_t)id*4] = make_uint2(l01, l23);
}

// ============================================================================
// Kernel 1: S-build.  Per CTA: one mt x all 8 nt tiles; Em bf16 planes loaded
// once, En double-buffered.  grid (8 mt, 32 g), 256 threads, 2 CTAs/SM.
// ============================================================================
#define SB_PITCH 72                          // bf16; 144 B rows (16-mult), conflict-free
#define SB_PLANE (128*SB_PITCH)
#define SB_TILE  (2*SB_PLANE)                // hi+lo = 36864 B
#define SB_SMEM  (3*SB_TILE*2)               // Em + 2 En stages = 110592 B

__global__ void __launch_bounds__(256,2) k_sbuild()
{
    extern __shared__ __nv_bfloat16 smh[];
    const uint32_t smb = smem_u32(smh);
    const int tid = threadIdx.x, lane = tid & 31, wid = tid >> 5;
    const int wy = wid >> 2, wx = wid & 3;
    const int mt = blockIdx.x, gb = blockIdx.y;

    const size_t embase = (size_t)(gb*MN + mt*128)*ED;
    const size_t egbase = (size_t)gb*MN*ED;

    // coverage: 2 planes x 128 rows x 8 ops = 2048 = 8 rounds x 256 thr
    auto copy_tile = [&](uint32_t base, size_t srcoff){
        #pragma unroll
        for (int r = 0; r < 8; r++){
            int id = r*256 + tid;
            int plane = id >> 10, rem = id & 1023;
            int row = rem >> 3, f = rem & 7;
            const __nv_bfloat16* src = (plane ? g_El : g_Eh) + srcoff + (size_t)row*ED + f*8;
            cpa16(base + plane*(SB_PLANE*2) + row*144 + f*16, src);
        }
    };

    copy_tile(smb, embase);
    copy_tile(smb + SB_TILE*2, egbase);
    CP_COMMIT();
    copy_tile(smb + 2*SB_TILE*2, egbase + (size_t)128*ED);
    CP_COMMIT();

    const int g = lane >> 2, t = lane & 3;
    const int rowbase = gb*MN + mt*128;
    float rsum_acc[4][2] = {};

    const __nv_bfloat16* EmH = smh;
    const __nv_bfloat16* EmL = smh + SB_PLANE;

    for (int nt = 0; nt < 8; nt++){
        if (nt < 7) { CP_WAIT(1); } else { CP_WAIT(0); }
        __syncthreads();

        const __nv_bfloat16* EnH = smh + (1 + (nt & 1))*SB_TILE;
        const __nv_bfloat16* EnL = EnH + SB_PLANE;
        float c4[4][4][4] = {};
        #pragma unroll
        for (int kk = 0; kk < 64; kk += 16)
            mma_step_bf16<SB_PITCH>(EmH, EmL, EnH, EnL, kk, wy, wx, lane, c4);
        __syncthreads();

        if (nt + 2 <= 7){
            copy_tile(smb + (1 + ((nt + 2) & 1))*SB_TILE*2, egbase + (size_t)((nt+2)*128)*ED);
            CP_COMMIT();
        }

        #pragma unroll
        for (int i = 0; i < 4; i++){
            #pragma unroll
            for (int h = 0; h < 2; h++){
                const int row = rowbase + wy*64 + i*16 + g + h*8;
                const size_t soff = (size_t)row*MN + nt*128;
                float rsum = 0.f;
                #pragma unroll
                for (int j = 0; j < 4; j++){
                    float v0 = fmaxf(c4[i][j][h*2+0], 0.f);
                    float v1 = fmaxf(c4[i][j][h*2+1], 0.f);
                    rsum += v0 + v1;
                    uint32_t h01, l01;
                    bsplit2(v0, v1, h01, l01);
                    const size_t o = soff + wx*32 + j*8 + 2*t;
                    *(uint32_t*)&g_Sh[o] = h01;
                    *(uint32_t*)&g_Sl[o] = l01;
                }
                rsum_acc[i][h] += rsum;
            }
        }
    }

    #pragma unroll
    for (int i = 0; i < 4; i++){
        #pragma unroll
        for (int h = 0; h < 2; h++){
            float rsum = rsum_acc[i][h];
            rsum += __shfl_xor_sync(0xFFFFFFFFu, rsum, 1);
            rsum += __shfl_xor_sync(0xFFFFFFFFu, rsum, 2);
            if (t == 0){
                const int row = rowbase + wy*64 + i*16 + g + h*8;
                g_degp[row*4 + wx] = rsum;
            }
        }
    }
}

// ============================================================================
// Kernel 2: dinv = rsqrt(1 + sum of 4 partials)
// ============================================================================
__global__ void k_dinv()
{
    const int i = blockIdx.x*256 + threadIdx.x;
    float s = 1.0f;
    #pragma unroll
    for (int j = 0; j < 4; j++) s += g_degp[i*4 + j];
    g_dinv[i] = rsqrtf(s);
}

// ============================================================================
// Kernel 3: Z = dinv ⊙ (In @ W^T).  K=128, 4 chunks, double-buffered.
// ============================================================================
#define GW_PITCH 40
#define GW_TILE  (128*GW_PITCH)
#define GW_STAGE (2*GW_TILE)
#define GW_SMEM  (2*GW_STAGE*4)         // 81920 B

__global__ void __launch_bounds__(256,2) k_gemmw(const float* __restrict__ xin,
                                                 const float* __restrict__ W,
                                                 int use_internal)
{
    extern __shared__ float sm[];
    const uint32_t smb = smem_u32(sm);
    const float* __restrict__ in = use_internal ? g_y : xin;
    const int tid = threadIdx.x, lane = tid & 31, wid = tid >> 5;
    const int wy = wid >> 2, wx = wid & 3;
    const int rbase = blockIdx.x*128;

    auto copy = [&](int c){
        const uint32_t ab = smb + (uint32_t)(c & 1)*GW_STAGE*4;
        const uint32_t bb = ab + GW_TILE*4;
        #pragma unroll
        for (int r = 0; r < 4; r++){
            int id = r*256 + tid;
            int m = id >> 3, f = id & 7;
            cpa16(ab + m*160 + f*16, in + (size_t)(rbase + m)*128 + c*32 + f*4);
            cpa16(bb + m*160 + f*16, W  + (size_t)m*128          + c*32 + f*4);
        }
        CP_COMMIT();
    };

    float c4[4][4][4] = {};
    copy(0);
    for (int c = 0; c < 4; c++){
        if (c < 3){ copy(c + 1); CP_WAIT(1); } else { CP_WAIT(0); }
        __syncthreads();
        const float* As = sm + (c & 1)*GW_STAGE;
        const float* Bs = As + GW_TILE;
        #pragma unroll
        for (int kk = 0; kk < 32; kk += 16)
            mma_step_f32<GW_PITCH, GW_PITCH>(As, Bs, kk, wy, wx, lane, c4);
        __syncthreads();
    }

    const int g = lane >> 2, t = lane & 3;
    #pragma unroll
    for (int i = 0; i < 4; i++){
        #pragma unroll
        for (int h = 0; h < 2; h++){
            const int row = rbase + wy*64 + i*16 + g + h*8;
            const float sc = g_dinv[row];
            const int gb = row >> 10, nloc = row & 1023;
            float* zr = g_z + (size_t)row*128;
            #pragma unroll
            for (int j = 0; j < 4; j++){
                const int col = wx*32 + j*8 + 2*t;
                float v0 = sc*c4[i][j][h*2], v1 = sc*c4[i][j][h*2+1];
                *(float2*)&zr[col] = make_float2(v0, v1);
                __nv_bfloat16 h0 = __float2bfloat16(v0);
                __nv_bfloat16 h1 = __float2bfloat16(v1);
                const size_t o0 = ((size_t)gb*DF + col    )*MN + nloc;
                const size_t o1 = ((size_t)gb*DF + col + 1)*MN + nloc;
                g_zth[o0] = h0;  g_ztl[o0] = __float2bfloat16(v0 - __bfloat162float(h0));
                g_zth[o1] = h1;  g_ztl[o1] = __float2bfloat16(v1 - __bfloat162float(h1));
            }
        }
    }
}

// ============================================================================
// Kernel 4: propagation.  out = relu(dinv⊙(S@Z + Z)).  K=1024: 32 chunks k32.
// 3-stage cp.async, ONE barrier per chunk.  Interleaved hi/lo rows: each smem
// row = [32 hi | 32 lo | 8 pad] bf16 = 144 B (16-mult; banks 4g+t conflict-free).
// grid (8 mt, 32 g), 256 threads, 2 CTAs/SM.
// ============================================================================
#define PR_PITCH 72
#define PR_MAT   (128*PR_PITCH)         // 9216 elems = 18432 B
#define PR_STAGE (2*PR_MAT)             // S + Zt = 36864 B
#define PR_NSTG  3
#define PR_SMEM  (PR_NSTG*PR_STAGE*2)   // 110592 B

__global__ void __launch_bounds__(256,2) k_prop(float* __restrict__ outext, int to_internal)
{
    extern __shared__ __nv_bfloat16 smh[];
    const uint32_t smb = smem_u32(smh);
    const int tid = threadIdx.x, lane = tid & 31, wid = tid >> 5;
    const int wy = wid >> 2, wx = wid & 3;
    const int mt = blockIdx.x, gb = blockIdx.y;
    float* __restrict__ dst = to_internal ? g_y : outext;

    const int mrow0 = gb*MN + mt*128;

    // coverage: 2 mats x 128 rows x 8 ops(16B) = 2048 = 8 rounds x 256 thr
    auto copy = [&](int c){
        const uint32_t sb = smb + (uint32_t)(c % PR_NSTG)*PR_STAGE*2;
        #pragma unroll
        for (int r = 0; r < 8; r++){
            int id = r*256 + tid;
            int mat = id >> 10, rem = id & 1023;
            int row = rem >> 3, o = rem & 7;
            int half = o >> 2, f = o & 3;
            const uint32_t dsta = sb + mat*(PR_MAT*2) + row*144 + half*64 + f*16;
            const __nv_bfloat16* src;
            if (mat == 0) src = (half ? g_Sl : g_Sh) + (size_t)(mrow0 + row)*MN + c*32 + f*8;
            else          src = (half ? g_ztl : g_zth) + ((size_t)gb*DF + row)*MN + c*32 + f*8;
            cpa16(dsta, src);
        }
        CP_COMMIT();
    };

    float c4[4][4][4] = {};
    copy(0); copy(1);
    for (int c = 0; c < 32; c++){
        if (c < 31) { CP_WAIT(1); } else { CP_WAIT(0); }
        __syncthreads();   // single barrier: stage (c+2)%3's readers (chunk c-1) passed here
        const __nv_bfloat16* A = smh + (size_t)(c % PR_NSTG)*PR_STAGE;
        const __nv_bfloat16* B = A + PR_MAT;
        #pragma unroll
        for (int kk = 0; kk < 32; kk += 16)
            mma_step_bf16<PR_PITCH>(A, A + 32, B, B + 32, kk, wy, wx, lane, c4);
        if (c + 2 < 32) copy(c + 2);
    }

    const int g = lane >> 2, t = lane & 3;
    #pragma unroll
    for (int i = 0; i < 4; i++){
        #pragma unroll
        for (int h = 0; h < 2; h++){
            const int row = mrow0 + wy*64 + i*16 + g + h*8;
            const float sc = g_dinv[row];
            const float* zr = g_z + (size_t)row*128;
            float* orow = dst + (size_t)row*128;
            #pragma unroll
            for (int j = 0; j < 4; j++){
                const int col = wx*32 + j*8 + 2*t;
                float2 z = *(const float2*)&zr[col];
                float2 o;
                o.x = fmaxf(sc*(c4[i][j][h*2]   + z.x), 0.f);
                o.y = fmaxf(sc*(c4[i][j][h*2+1] + z.y), 0.f);
                *(float2*)&orow[col] = o;
            }
        }
    }
}

// ============================================================================
extern "C" void kernel_launch(void* const* d_in, const int* in_sizes, int n_in,
                              void* d_out, int out_size)
{
    (void)in_sizes; (void)n_in; (void)out_size;
    const float* X  = (const float*)d_in[0];
    const float* E  = (const float*)d_in[1];
    const float* W1 = (const float*)d_in[2];
    const float* W2 = (const float*)d_in[3];
    float* out = (float*)d_out;

    cudaFuncSetAttribute(k_sbuild, cudaFuncAttributeMaxDynamicSharedMemorySize, SB_SMEM);
    cudaFuncSetAttribute(k_gemmw,  cudaFuncAttributeMaxDynamicSharedMemorySize, GW_SMEM);
    cudaFuncSetAttribute(k_prop,   cudaFuncAttributeMaxDynamicSharedMemorySize, PR_SMEM);

    k_esplit<<<2048, 256>>>(E);
    k_sbuild<<<dim3(8, 32), 256, SB_SMEM>>>();
    k_dinv  <<<NROWS/256, 256>>>();
    k_gemmw <<<256, 256, GW_SMEM>>>(X, W1, 0);
    k_prop  <<<dim3(8, 32), 256, PR_SMEM>>>(nullptr, 1);
    k_gemmw <<<256, 256, GW_SMEM>>>(nullptr, W2, 1);
    k_prop  <<<dim3(8, 32), 256, PR_SMEM>>>(out, 0);
}

// round 12
// speedup vs baseline: 1.1531x; 1.0201x over previous
#include <cuda_runtime.h>
#include <cuda_bf16.h>
#include <cstdint>

#define BATCH 32
#define MN    1024
#define DF    128
#define ED    64
#define NROWS (BATCH*MN)   // 32768

// ---------------- device scratch (no runtime allocation allowed) ----------------
__device__ __align__(16) __nv_bfloat16 g_Eh[(size_t)NROWS*ED];      // 4 MB
__device__ __align__(16) __nv_bfloat16 g_El[(size_t)NROWS*ED];      // 4 MB
__device__ __align__(16) __nv_bfloat16 g_Sh[(size_t)BATCH*MN*MN];   // 64 MB
__device__ __align__(16) __nv_bfloat16 g_Sl[(size_t)BATCH*MN*MN];   // 64 MB
__device__ float         g_degp[NROWS*4];
__device__ float         g_dinv[NROWS];
__device__ float         g_z  [(size_t)NROWS*DF];
__device__ __align__(16) __nv_bfloat16 g_zth[(size_t)BATCH*DF*MN];  // Z^T hi [g][d][n]
__device__ __align__(16) __nv_bfloat16 g_ztl[(size_t)BATCH*DF*MN];  // Z^T lo
__device__ float         g_y  [(size_t)NROWS*DF];

// ---------------- helpers ----------------
__device__ __forceinline__ uint32_t smem_u32(const void* p){
    uint32_t a;
    asm("{ .reg .u64 t; cvta.to.shared.u64 t, %1; cvt.u32.u64 %0, t; }" : "=r"(a) : "l"(p));
    return a;
}
__device__ __forceinline__ void cpa16(uint32_t d, const void* s){
    asm volatile("cp.async.cg.shared.global [%0], [%1], 16;" :: "r"(d), "l"(s));
}
#define CP_COMMIT() asm volatile("cp.async.commit_group;" ::: "memory")
#define CP_WAIT(n)  asm volatile("cp.async.wait_group %0;" :: "n"(n) : "memory")

// bf16 2-term split of a pair (v0 -> low half, v1 -> high half of packed reg).
__device__ __forceinline__ void bsplit2(float v0, float v1, uint32_t& h01, uint32_t& l01){
    asm("cvt.rn.bf16x2.f32 %0, %1, %2;" : "=r"(h01) : "f"(v1), "f"(v0));
    float h0 = __uint_as_float(h01 << 16);
    float h1 = __uint_as_float(h01 & 0xFFFF0000u);
    float l0 = v0 - h0, l1 = v1 - h1;
    asm("cvt.rn.bf16x2.f32 %0, %1, %2;" : "=r"(l01) : "f"(l1), "f"(l0));
}

__device__ __forceinline__ void mma16(float c[4], const uint32_t a[4], const uint32_t b[2]){
    asm volatile(
        "mma.sync.aligned.m16n8k16.row.col.f32.bf16.bf16.f32 "
        "{%0,%1,%2,%3}, {%4,%5,%6,%7}, {%8,%9}, {%0,%1,%2,%3};"
        : "+f"(c[0]), "+f"(c[1]), "+f"(c[2]), "+f"(c[3])
        : "r"(a[0]), "r"(a[1]), "r"(a[2]), "r"(a[3]), "r"(b[0]), "r"(b[1]));
}

__device__ __forceinline__ void mma3pass(float c[4][4][4],
    const uint32_t ah[4][4], const uint32_t al[4][4],
    const uint32_t bh[4][2], const uint32_t bl[4][2])
{
    #pragma unroll
    for (int j = 0; j < 4; j++)
        #pragma unroll
        for (int i = 0; i < 4; i++) mma16(c[i][j], ah[i], bh[j]);
    #pragma unroll
    for (int j = 0; j < 4; j++)
        #pragma unroll
        for (int i = 0; i < 4; i++) mma16(c[i][j], al[i], bh[j]);
    #pragma unroll
    for (int j = 0; j < 4; j++)
        #pragma unroll
        for (int i = 0; i < 4; i++) mma16(c[i][j], ah[i], bl[j]);
}

// One k16 step from fp32 smem tiles (A [m][k] pitch PA, B [n][k] pitch PB).
template<int PA, int PB>
__device__ __forceinline__ void mma_step_f32(const float* __restrict__ As,
                                             const float* __restrict__ Bs,
                                             int kk, int wy, int wx, int lane,
                                             float c[4][4][4])
{
    const int g = lane >> 2, t = lane & 3;
    uint32_t ah[4][4], al[4][4], bh[4][2], bl[4][2];
    #pragma unroll
    for (int i = 0; i < 4; i++){
        const float* ap = As + (wy*64 + i*16 + g)*PA + kk + 2*t;
        float2 v;
        v = *(const float2*)(ap);            bsplit2(v.x, v.y, ah[i][0], al[i][0]);
        v = *(const float2*)(ap + 8*PA);     bsplit2(v.x, v.y, ah[i][1], al[i][1]);
        v = *(const float2*)(ap + 8);        bsplit2(v.x, v.y, ah[i][2], al[i][2]);
        v = *(const float2*)(ap + 8*PA + 8); bsplit2(v.x, v.y, ah[i][3], al[i][3]);
    }
    #pragma unroll
    for (int j = 0; j < 4; j++){
        const float* bp = Bs + (wx*32 + j*8 + g)*PB + kk + 2*t;
        float2 v;
        v = *(const float2*)(bp);     bsplit2(v.x, v.y, bh[j][0], bl[j][0]);
        v = *(const float2*)(bp + 8); bsplit2(v.x, v.y, bh[j][1], bl[j][1]);
    }
    mma3pass(c, ah, al, bh, bl);
}

// One k16 step from pre-split bf16 planes (A [m][k], B [n][k]; pitch P elems).
// Al/Bl may be Ah+32/Bh+32 (interleaved rows) or separate planes.
template<int P>
__device__ __forceinline__ void mma_step_bf16(const __nv_bfloat16* __restrict__ Ah,
                                              const __nv_bfloat16* __restrict__ Al,
                                              const __nv_bfloat16* __restrict__ Bh,
                                              const __nv_bfloat16* __restrict__ Bl,
                                              int kk, int wy, int wx, int lane,
                                              float c[4][4][4])
{
    const int g = lane >> 2, t = lane & 3;
    uint32_t ah[4][4], al[4][4], bh[4][2], bl[4][2];
    #pragma unroll
    for (int i = 0; i < 4; i++){
        const int r0 = (wy*64 + i*16 + g)*P + kk + 2*t;
        ah[i][0] = *(const uint32_t*)(Ah + r0);
        ah[i][1] = *(const uint32_t*)(Ah + r0 + 8*P);
        ah[i][2] = *(const uint32_t*)(Ah + r0 + 8);
        ah[i][3] = *(const uint32_t*)(Ah + r0 + 8*P + 8);
        al[i][0] = *(const uint32_t*)(Al + r0);
        al[i][1] = *(const uint32_t*)(Al + r0 + 8*P);
        al[i][2] = *(const uint32_t*)(Al + r0 + 8);
        al[i][3] = *(const uint32_t*)(Al + r0 + 8*P + 8);
    }
    #pragma unroll
    for (int j = 0; j < 4; j++){
        const int rb = (wx*32 + j*8 + g)*P + kk + 2*t;
        bh[j][0] = *(const uint32_t*)(Bh + rb);
        bh[j][1] = *(const uint32_t*)(Bh + rb + 8);
        bl[j][0] = *(const uint32_t*)(Bl + rb);
        bl[j][1] = *(const uint32_t*)(Bl + rb + 8);
    }
    mma3pass(c, ah, al, bh, bl);
}

// ============================================================================
// Kernel 0: split E into bf16 hi/lo planes.
// ============================================================================
__global__ void k_esplit(const float* __restrict__ E)
{
    const int id = blockIdx.x*256 + threadIdx.x;      // 524288 float4 total
    float4 v = *(const float4*)(E + (size_t)id*4);
    uint32_t h01, l01, h23, l23;
    bsplit2(v.x, v.y, h01, l01);
    bsplit2(v.z, v.w, h23, l23);
    *(uint2*)&g_Eh[(size_t)id*4] = make_uint2(h01, h23);
    *(uint2*)&g_El[(size_t)id*4] = make_uint2(l01, l23);
}

// ============================================================================
// Kernel 1: S-build.  Per CTA: one mt x all 8 nt tiles; Em bf16 planes loaded
// once, En double-buffered.  grid (8 mt, 32 g), 256 threads, 2 CTAs/SM.
// ============================================================================
#define SB_PITCH 72                          // bf16; 144 B rows (16-mult), conflict-free
#define SB_PLANE (128*SB_PITCH)
#define SB_TILE  (2*SB_PLANE)                // hi+lo = 36864 B
#define SB_SMEM  (3*SB_TILE*2)               // Em + 2 En stages = 110592 B

__global__ void __launch_bounds__(256,2) k_sbuild()
{
    extern __shared__ __nv_bfloat16 smh[];
    const uint32_t smb = smem_u32(smh);
    const int tid = threadIdx.x, lane = tid & 31, wid = tid >> 5;
    const int wy = wid >> 2, wx = wid & 3;
    const int mt = blockIdx.x, gb = blockIdx.y;

    const size_t embase = (size_t)(gb*MN + mt*128)*ED;
    const size_t egbase = (size_t)gb*MN*ED;

    // coverage: 2 planes x 128 rows x 8 ops = 2048 = 8 rounds x 256 thr
    auto copy_tile = [&](uint32_t base, size_t srcoff){
        #pragma unroll
        for (int r = 0; r < 8; r++){
            int id = r*256 + tid;
            int plane = id >> 10, rem = id & 1023;
            int row = rem >> 3, f = rem & 7;
            const __nv_bfloat16* src = (plane ? g_El : g_Eh) + srcoff + (size_t)row*ED + f*8;
            cpa16(base + plane*(SB_PLANE*2) + row*144 + f*16, src);
        }
    };

    copy_tile(smb, embase);
    copy_tile(smb + SB_TILE*2, egbase);
    CP_COMMIT();
    copy_tile(smb + 2*SB_TILE*2, egbase + (size_t)128*ED);
    CP_COMMIT();

    const int g = lane >> 2, t = lane & 3;
    const int rowbase = gb*MN + mt*128;
    float rsum_acc[4][2] = {};

    const __nv_bfloat16* EmH = smh;
    const __nv_bfloat16* EmL = smh + SB_PLANE;

    for (int nt = 0; nt < 8; nt++){
        if (nt < 7) { CP_WAIT(1); } else { CP_WAIT(0); }
        __syncthreads();

        const __nv_bfloat16* EnH = smh + (1 + (nt & 1))*SB_TILE;
        const __nv_bfloat16* EnL = EnH + SB_PLANE;
        float c4[4][4][4] = {};
        #pragma unroll
        for (int kk = 0; kk < 64; kk += 16)
            mma_step_bf16<SB_PITCH>(EmH, EmL, EnH, EnL, kk, wy, wx, lane, c4);
        __syncthreads();

        if (nt + 2 <= 7){
            copy_tile(smb + (1 + ((nt + 2) & 1))*SB_TILE*2, egbase + (size_t)((nt+2)*128)*ED);
            CP_COMMIT();
        }

        #pragma unroll
        for (int i = 0; i < 4; i++){
            #pragma unroll
            for (int h = 0; h < 2; h++){
                const int row = rowbase + wy*64 + i*16 + g + h*8;
                const size_t soff = (size_t)row*MN + nt*128;
                float rsum = 0.f;
                #pragma unroll
                for (int j = 0; j < 4; j++){
                    float v0 = fmaxf(c4[i][j][h*2+0], 0.f);
                    float v1 = fmaxf(c4[i][j][h*2+1], 0.f);
                    rsum += v0 + v1;
                    uint32_t h01, l01;
                    bsplit2(v0, v1, h01, l01);
                    const size_t o = soff + wx*32 + j*8 + 2*t;
                    *(uint32_t*)&g_Sh[o] = h01;
                    *(uint32_t*)&g_Sl[o] = l01;
                }
                rsum_acc[i][h] += rsum;
            }
        }
    }

    #pragma unroll
    for (int i = 0; i < 4; i++){
        #pragma unroll
        for (int h = 0; h < 2; h++){
            float rsum = rsum_acc[i][h];
            rsum += __shfl_xor_sync(0xFFFFFFFFu, rsum, 1);
            rsum += __shfl_xor_sync(0xFFFFFFFFu, rsum, 2);
            if (t == 0){
                const int row = rowbase + wy*64 + i*16 + g + h*8;
                g_degp[row*4 + wx] = rsum;
            }
        }
    }
}

// ============================================================================
// Kernel 2: dinv = rsqrt(1 + sum of 4 partials)
// ============================================================================
__global__ void k_dinv()
{
    const int i = blockIdx.x*256 + threadIdx.x;
    float s = 1.0f;
    #pragma unroll
    for (int j = 0; j < 4; j++) s += g_degp[i*4 + j];
    g_dinv[i] = rsqrtf(s);
}

// ============================================================================
// Kernel 3: Z = dinv ⊙ (In @ W^T).  K=128, 4 chunks, double-buffered.
// Epilogue: smem-staged transpose -> fully coalesced Z^T plane stores.
// ============================================================================
#define GW_PITCH 40
#define GW_TILE  (128*GW_PITCH)
#define GW_STAGE (2*GW_TILE)
#define GW_SMEM  (2*GW_STAGE*4)         // 81920 B (also >= 67584 B transpose buffer)
#define TP 264                          // transpose pitch (bf16): [128 hi | 128 lo | 8 pad]

__global__ void __launch_bounds__(256,2) k_gemmw(const float* __restrict__ xin,
                                                 const float* __restrict__ W,
                                                 int use_internal)
{
    extern __shared__ float sm[];
    const uint32_t smb = smem_u32(sm);
    const float* __restrict__ in = use_internal ? g_y : xin;
    const int tid = threadIdx.x, lane = tid & 31, wid = tid >> 5;
    const int wy = wid >> 2, wx = wid & 3;
    const int rbase = blockIdx.x*128;

    auto copy = [&](int c){
        const uint32_t ab = smb + (uint32_t)(c & 1)*GW_STAGE*4;
        const uint32_t bb = ab + GW_TILE*4;
        #pragma unroll
        for (int r = 0; r < 4; r++){
            int id = r*256 + tid;
            int m = id >> 3, f = id & 7;
            cpa16(ab + m*160 + f*16, in + (size_t)(rbase + m)*128 + c*32 + f*4);
            cpa16(bb + m*160 + f*16, W  + (size_t)m*128          + c*32 + f*4);
        }
        CP_COMMIT();
    };

    float c4[4][4][4] = {};
    copy(0);
    for (int c = 0; c < 4; c++){
        if (c < 3){ copy(c + 1); CP_WAIT(1); } else { CP_WAIT(0); }
        __syncthreads();
        const float* As = sm + (c & 1)*GW_STAGE;
        const float* Bs = As + GW_TILE;
        #pragma unroll
        for (int kk = 0; kk < 32; kk += 16)
            mma_step_f32<GW_PITCH, GW_PITCH>(As, Bs, kk, wy, wx, lane, c4);
        __syncthreads();
    }

    const int g = lane >> 2, t = lane & 3;
    const int gb = rbase >> 10;
    const int nbase = rbase & 1023;
    __nv_bfloat16* tb = (__nv_bfloat16*)sm;   // reuse stage smem: 128 x TP bf16

    // phase 1: scale, write g_z (coalesced f32), stage split planes transposed in smem
    #pragma unroll
    for (int i = 0; i < 4; i++){
        #pragma unroll
        for (int h = 0; h < 2; h++){
            const int lrow = wy*64 + i*16 + g + h*8;
            const float sc = g_dinv[rbase + lrow];
            float* zr = g_z + (size_t)(rbase + lrow)*128;
            #pragma unroll
            for (int j = 0; j < 4; j++){
                const int col = wx*32 + j*8 + 2*t;
                float v0 = sc*c4[i][j][h*2], v1 = sc*c4[i][j][h*2+1];
                *(float2*)&zr[col] = make_float2(v0, v1);
                __nv_bfloat16 h0 = __float2bfloat16(v0);
                __nv_bfloat16 h1 = __float2bfloat16(v1);
                tb[(col    )*TP + lrow]       = h0;
                tb[(col + 1)*TP + lrow]       = h1;
                tb[(col    )*TP + 128 + lrow] = __float2bfloat16(v0 - __bfloat162float(h0));
                tb[(col + 1)*TP + 128 + lrow] = __float2bfloat16(v1 - __bfloat162float(h1));
            }
        }
    }
    __syncthreads();

    // phase 2: coalesced 16B stores.  coverage: 2 planes x 128 d x 16 ops = 4096
    //          = 16 rounds x 256 thr
    #pragma unroll
    for (int r = 0; r < 16; r++){
        int id = r*256 + tid;
        int plane = id >> 11, rem = id & 2047;
        int d = rem >> 4, f = rem & 15;
        uint4 v = *(const uint4*)&tb[d*TP + plane*128 + f*8];
        __nv_bfloat16* dstp = (plane ? g_ztl : g_zth) + ((size_t)gb*DF + d)*MN + nbase + f*8;
        *(uint4*)dstp = v;
    }
}

// ============================================================================
// Kernel 4: propagation.  out = relu(dinv⊙(S@Z + Z)).  K=1024: 32 chunks k32.
// 3-stage cp.async, ONE barrier per chunk.  Interleaved hi/lo rows: each smem
// row = [32 hi | 32 lo | 8 pad] bf16 = 144 B (16-mult; banks conflict-free).
// grid (8 mt, 32 g), 256 threads, 2 CTAs/SM.
// ============================================================================
#define PR_PITCH 72
#define PR_MAT   (128*PR_PITCH)         // 9216 elems = 18432 B
#define PR_STAGE (2*PR_MAT)             // S + Zt = 36864 B
#define PR_NSTG  3
#define PR_SMEM  (PR_NSTG*PR_STAGE*2)   // 110592 B

__global__ void __launch_bounds__(256,2) k_prop(float* __restrict__ outext, int to_internal)
{
    extern __shared__ __nv_bfloat16 smh[];
    const uint32_t smb = smem_u32(smh);
    const int tid = threadIdx.x, lane = tid & 31, wid = tid >> 5;
    const int wy = wid >> 2, wx = wid & 3;
    const int mt = blockIdx.x, gb = blockIdx.y;
    float* __restrict__ dst = to_internal ? g_y : outext;

    const int mrow0 = gb*MN + mt*128;

    // coverage: 2 mats x 128 rows x 8 ops(16B) = 2048 = 8 rounds x 256 thr
    auto copy = [&](int c){
        const uint32_t sb = smb + (uint32_t)(c % PR_NSTG)*PR_STAGE*2;
        #pragma unroll
        for (int r = 0; r < 8; r++){
            int id = r*256 + tid;
            int mat = id >> 10, rem = id & 1023;
            int row = rem >> 3, o = rem & 7;
            int half = o >> 2, f = o & 3;
            const uint32_t dsta = sb + mat*(PR_MAT*2) + row*144 + half*64 + f*16;
            const __nv_bfloat16* src;
            if (mat == 0) src = (half ? g_Sl : g_Sh) + (size_t)(mrow0 + row)*MN + c*32 + f*8;
            else          src = (half ? g_ztl : g_zth) + ((size_t)gb*DF + row)*MN + c*32 + f*8;
            cpa16(dsta, src);
        }
        CP_COMMIT();
    };

    float c4[4][4][4] = {};
    copy(0); copy(1);
    for (int c = 0; c < 32; c++){
        if (c < 31) { CP_WAIT(1); } else { CP_WAIT(0); }
        __syncthreads();   // single barrier: stage (c+2)%3's readers (chunk c-1) passed here
        const __nv_bfloat16* A = smh + (size_t)(c % PR_NSTG)*PR_STAGE;
        const __nv_bfloat16* B = A + PR_MAT;
        #pragma unroll
        for (int kk = 0; kk < 32; kk += 16)
            mma_step_bf16<PR_PITCH>(A, A + 32, B, B + 32, kk, wy, wx, lane, c4);
        if (c + 2 < 32) copy(c + 2);
    }

    const int g = lane >> 2, t = lane & 3;
    #pragma unroll
    for (int i = 0; i < 4; i++){
        #pragma unroll
        for (int h = 0; h < 2; h++){
            const int row = mrow0 + wy*64 + i*16 + g + h*8;
            const float sc = g_dinv[row];
            const float* zr = g_z + (size_t)row*128;
            float* orow = dst + (size_t)row*128;
            #pragma unroll
            for (int j = 0; j < 4; j++){
                const int col = wx*32 + j*8 + 2*t;
                float2 z = *(const float2*)&zr[col];
                float2 o;
                o.x = fmaxf(sc*(c4[i][j][h*2]   + z.x), 0.f);
                o.y = fmaxf(sc*(c4[i][j][h*2+1] + z.y), 0.f);
                *(float2*)&orow[col] = o;
            }
        }
    }
}

// ============================================================================
extern "C" void kernel_launch(void* const* d_in, const int* in_sizes, int n_in,
                              void* d_out, int out_size)
{
    (void)in_sizes; (void)n_in; (void)out_size;
    const float* X  = (const float*)d_in[0];
    const float* E  = (const float*)d_in[1];
    const float* W1 = (const float*)d_in[2];
    const float* W2 = (const float*)d_in[3];
    float* out = (float*)d_out;

    cudaFuncSetAttribute(k_sbuild, cudaFuncAttributeMaxDynamicSharedMemorySize, SB_SMEM);
    cudaFuncSetAttribute(k_gemmw,  cudaFuncAttributeMaxDynamicSharedMemorySize, GW_SMEM);
    cudaFuncSetAttribute(k_prop,   cudaFuncAttributeMaxDynamicSharedMemorySize, PR_SMEM);

    k_esplit<<<2048, 256>>>(E);
    k_sbuild<<<dim3(8, 32), 256, SB_SMEM>>>();
    k_dinv  <<<NROWS/256, 256>>>();
    k_gemmw <<<256, 256, GW_SMEM>>>(X, W1, 0);
    k_prop  <<<dim3(8, 32), 256, PR_SMEM>>>(nullptr, 1);
    k_gemmw <<<256, 256, GW_SMEM>>>(nullptr, W2, 1);
    k_prop  <<<dim3(8, 32), 256, PR_SMEM>>>(out, 0);
}

// round 13
// speedup vs baseline: 1.1882x; 1.0304x over previous
#include <cuda_runtime.h>
#include <cuda_bf16.h>
#include <cstdint>

#define BATCH 32
#define MN    1024
#define DF    128
#define ED    64
#define NROWS (BATCH*MN)   // 32768

// ---------------- device scratch (no runtime allocation allowed) ----------------
__device__ __align__(16) __nv_bfloat16 g_Eh[(size_t)NROWS*ED];      // 4 MB
__device__ __align__(16) __nv_bfloat16 g_El[(size_t)NROWS*ED];      // 4 MB
__device__ __align__(16) __nv_bfloat16 g_Sh[(size_t)BATCH*MN*MN];   // 64 MB
__device__ __align__(16) __nv_bfloat16 g_Sl[(size_t)BATCH*MN*MN];   // 64 MB
__device__ float         g_degp[NROWS*4];
__device__ float         g_dinv[NROWS];
__device__ float         g_z  [(size_t)NROWS*DF];
__device__ __align__(16) __nv_bfloat16 g_zth[(size_t)BATCH*DF*MN];  // Z^T hi [g][d][n]
__device__ __align__(16) __nv_bfloat16 g_ztl[(size_t)BATCH*DF*MN];  // Z^T lo
__device__ float         g_y  [(size_t)NROWS*DF];

// ---------------- helpers ----------------
__device__ __forceinline__ uint32_t smem_u32(const void* p){
    uint32_t a;
    asm("{ .reg .u64 t; cvta.to.shared.u64 t, %1; cvt.u32.u64 %0, t; }" : "=r"(a) : "l"(p));
    return a;
}
__device__ __forceinline__ void cpa16(uint32_t d, const void* s){
    asm volatile("cp.async.cg.shared.global [%0], [%1], 16;" :: "r"(d), "l"(s));
}
#define CP_COMMIT() asm volatile("cp.async.commit_group;" ::: "memory")
#define CP_WAIT(n)  asm volatile("cp.async.wait_group %0;" :: "n"(n) : "memory")

__device__ __forceinline__ void ldsm_x4(uint32_t& r0, uint32_t& r1, uint32_t& r2,
                                        uint32_t& r3, uint32_t addr){
    asm volatile("ldmatrix.sync.aligned.m8n8.x4.shared.b16 {%0,%1,%2,%3}, [%4];"
        : "=r"(r0), "=r"(r1), "=r"(r2), "=r"(r3) : "r"(addr));
}

// bf16 2-term split of a pair (v0 -> low half, v1 -> high half of packed reg).
__device__ __forceinline__ void bsplit2(float v0, float v1, uint32_t& h01, uint32_t& l01){
    asm("cvt.rn.bf16x2.f32 %0, %1, %2;" : "=r"(h01) : "f"(v1), "f"(v0));
    float h0 = __uint_as_float(h01 << 16);
    float h1 = __uint_as_float(h01 & 0xFFFF0000u);
    float l0 = v0 - h0, l1 = v1 - h1;
    asm("cvt.rn.bf16x2.f32 %0, %1, %2;" : "=r"(l01) : "f"(l1), "f"(l0));
}

__device__ __forceinline__ void mma16(float c[4], const uint32_t a[4], const uint32_t b[2]){
    asm volatile(
        "mma.sync.aligned.m16n8k16.row.col.f32.bf16.bf16.f32 "
        "{%0,%1,%2,%3}, {%4,%5,%6,%7}, {%8,%9}, {%0,%1,%2,%3};"
        : "+f"(c[0]), "+f"(c[1]), "+f"(c[2]), "+f"(c[3])
        : "r"(a[0]), "r"(a[1]), "r"(a[2]), "r"(a[3]), "r"(b[0]), "r"(b[1]));
}

// One k16 step via ldmatrix.  A: [m][k] pitch P elems, hi plane at Aaddr, lo at
// +loA bytes.  B: [n][k] pitch P, hi at Baddr, lo at +loB bytes.  B hi/lo merged
// into a single x4 per j: mats {bh(k0), bh(k8), bl(k0), bl(k8)}.
template<int P>
__device__ __forceinline__ void mma_step_ldsm(uint32_t Aaddr, uint32_t Baddr,
                                              uint32_t loA, uint32_t loB,
                                              int kk, int wy, int wx, int lane,
                                              float c4[4][4][4])
{
    uint32_t ah[4][4], al[4][4], b4[4][4];
    const uint32_t aoff = Aaddr +
        (uint32_t)(((wy*64 + (lane & 15))*P + kk + ((lane >> 4)*8))*2);
    #pragma unroll
    for (int i = 0; i < 4; i++){
        ldsm_x4(ah[i][0], ah[i][1], ah[i][2], ah[i][3], aoff + i*(16*P*2));
        ldsm_x4(al[i][0], al[i][1], al[i][2], al[i][3], aoff + i*(16*P*2) + loA);
    }
    const uint32_t boff = Baddr +
        (uint32_t)(((wx*32 + (lane & 7))*P + kk + (((lane >> 3) & 1)*8))*2)
        + (uint32_t)(lane >> 4)*loB;
    #pragma unroll
    for (int j = 0; j < 4; j++)
        ldsm_x4(b4[j][0], b4[j][1], b4[j][2], b4[j][3], boff + j*(8*P*2));

    // 3-pass split product: hh, lh, hl
    #pragma unroll
    for (int j = 0; j < 4; j++)
        #pragma unroll
        for (int i = 0; i < 4; i++) mma16(c4[i][j], ah[i], &b4[j][0]);
    #pragma unroll
    for (int j = 0; j < 4; j++)
        #pragma unroll
        for (int i = 0; i < 4; i++) mma16(c4[i][j], al[i], &b4[j][0]);
    #pragma unroll
    for (int j = 0; j < 4; j++)
        #pragma unroll
        for (int i = 0; i < 4; i++) mma16(c4[i][j], ah[i], &b4[j][2]);
}

// One k16 step from fp32 smem tiles (A [m][k] pitch PA, B [n][k] pitch PB).
template<int PA, int PB>
__device__ __forceinline__ void mma_step_f32(const float* __restrict__ As,
                                             const float* __restrict__ Bs,
                                             int kk, int wy, int wx, int lane,
                                             float c4[4][4][4])
{
    const int g = lane >> 2, t = lane & 3;
    uint32_t ah[4][4], al[4][4], bh[4][2], bl[4][2];
    #pragma unroll
    for (int i = 0; i < 4; i++){
        const float* ap = As + (wy*64 + i*16 + g)*PA + kk + 2*t;
        float2 v;
        v = *(const float2*)(ap);            bsplit2(v.x, v.y, ah[i][0], al[i][0]);
        v = *(const float2*)(ap + 8*PA);     bsplit2(v.x, v.y, ah[i][1], al[i][1]);
        v = *(const float2*)(ap + 8);        bsplit2(v.x, v.y, ah[i][2], al[i][2]);
        v = *(const float2*)(ap + 8*PA + 8); bsplit2(v.x, v.y, ah[i][3], al[i][3]);
    }
    #pragma unroll
    for (int j = 0; j < 4; j++){
        const float* bp = Bs + (wx*32 + j*8 + g)*PB + kk + 2*t;
        float2 v;
        v = *(const float2*)(bp);     bsplit2(v.x, v.y, bh[j][0], bl[j][0]);
        v = *(const float2*)(bp + 8); bsplit2(v.x, v.y, bh[j][1], bl[j][1]);
    }
    #pragma unroll
    for (int j = 0; j < 4; j++)
        #pragma unroll
        for (int i = 0; i < 4; i++) mma16(c4[i][j], ah[i], bh[j]);
    #pragma unroll
    for (int j = 0; j < 4; j++)
        #pragma unroll
        for (int i = 0; i < 4; i++) mma16(c4[i][j], al[i], bh[j]);
    #pragma unroll
    for (int j = 0; j < 4; j++)
        #pragma unroll
        for (int i = 0; i < 4; i++) mma16(c4[i][j], ah[i], bl[j]);
}

// ============================================================================
// Kernel 0: split E into bf16 hi/lo planes.
// ============================================================================
__global__ void k_esplit(const float* __restrict__ E)
{
    const int id = blockIdx.x*256 + threadIdx.x;      // 524288 float4 total
    float4 v = *(const float4*)(E + (size_t)id*4);
    uint32_t h01, l01, h23, l23;
    bsplit2(v.x, v.y, h01, l01);
    bsplit2(v.z, v.w, h23, l23);
    *(uint2*)&g_Eh[(size_t)id*4] = make_uint2(h01, h23);
    *(uint2*)&g_El[(size_t)id*4] = make_uint2(l01, l23);
}

// ============================================================================
// Kernel 1: S-build.  Per CTA: one mt x all 8 nt tiles; Em bf16 planes loaded
// once, En double-buffered.  grid (8 mt, 32 g), 256 threads, 2 CTAs/SM.
// ============================================================================
#define SB_PITCH 72                          // bf16; 144 B rows, ldmatrix conflict-free
#define SB_PLANE (128*SB_PITCH)
#define SB_TILE  (2*SB_PLANE)                // hi+lo = 36864 B
#define SB_SMEM  (3*SB_TILE*2)               // Em + 2 En stages = 110592 B
#define SB_LO    (SB_PLANE*2)                // lo plane byte offset = 18432

__global__ void __launch_bounds__(256,2) k_sbuild()
{
    extern __shared__ __nv_bfloat16 smh[];
    const uint32_t smb = smem_u32(smh);
    const int tid = threadIdx.x, lane = tid & 31, wid = tid >> 5;
    const int wy = wid >> 2, wx = wid & 3;
    const int mt = blockIdx.x, gb = blockIdx.y;

    const size_t embase = (size_t)(gb*MN + mt*128)*ED;
    const size_t egbase = (size_t)gb*MN*ED;

    // coverage: 2 planes x 128 rows x 8 ops = 2048 = 8 rounds x 256 thr
    auto copy_tile = [&](uint32_t base, size_t srcoff){
        #pragma unroll
        for (int r = 0; r < 8; r++){
            int id = r*256 + tid;
            int plane = id >> 10, rem = id & 1023;
            int row = rem >> 3, f = rem & 7;
            const __nv_bfloat16* src = (plane ? g_El : g_Eh) + srcoff + (size_t)row*ED + f*8;
            cpa16(base + plane*SB_LO + row*144 + f*16, src);
        }
    };

    copy_tile(smb, embase);
    copy_tile(smb + SB_TILE*2, egbase);
    CP_COMMIT();
    copy_tile(smb + 2*SB_TILE*2, egbase + (size_t)128*ED);
    CP_COMMIT();

    const int g = lane >> 2, t = lane & 3;
    const int rowbase = gb*MN + mt*128;
    float rsum_acc[4][2] = {};

    for (int nt = 0; nt < 8; nt++){
        if (nt < 7) { CP_WAIT(1); } else { CP_WAIT(0); }
        __syncthreads();

        const uint32_t enaddr = smb + (1 + (nt & 1))*SB_TILE*2;
        float c4[4][4][4] = {};
        #pragma unroll
        for (int kk = 0; kk < 64; kk += 16)
            mma_step_ldsm<SB_PITCH>(smb, enaddr, SB_LO, SB_LO, kk, wy, wx, lane, c4);
        __syncthreads();

        if (nt + 2 <= 7){
            copy_tile(smb + (1 + ((nt + 2) & 1))*SB_TILE*2, egbase + (size_t)((nt+2)*128)*ED);
            CP_COMMIT();
        }

        #pragma unroll
        for (int i = 0; i < 4; i++){
            #pragma unroll
            for (int h = 0; h < 2; h++){
                const int row = rowbase + wy*64 + i*16 + g + h*8;
                const size_t soff = (size_t)row*MN + nt*128;
                float rsum = 0.f;
                #pragma unroll
                for (int j = 0; j < 4; j++){
                    float v0 = fmaxf(c4[i][j][h*2+0], 0.f);
                    float v1 = fmaxf(c4[i][j][h*2+1], 0.f);
                    rsum += v0 + v1;
                    uint32_t h01, l01;
                    bsplit2(v0, v1, h01, l01);
                    const size_t o = soff + wx*32 + j*8 + 2*t;
                    *(uint32_t*)&g_Sh[o] = h01;
                    *(uint32_t*)&g_Sl[o] = l01;
                }
                rsum_acc[i][h] += rsum;
            }
        }
    }

    #pragma unroll
    for (int i = 0; i < 4; i++){
        #pragma unroll
        for (int h = 0; h < 2; h++){
            float rsum = rsum_acc[i][h];
            rsum += __shfl_xor_sync(0xFFFFFFFFu, rsum, 1);
            rsum += __shfl_xor_sync(0xFFFFFFFFu, rsum, 2);
            if (t == 0){
                const int row = rowbase + wy*64 + i*16 + g + h*8;
                g_degp[row*4 + wx] = rsum;
            }
        }
    }
}

// ============================================================================
// Kernel 2: dinv = rsqrt(1 + sum of 4 partials)
// ============================================================================
__global__ void k_dinv()
{
    const int i = blockIdx.x*256 + threadIdx.x;
    float s = 1.0f;
    #pragma unroll
    for (int j = 0; j < 4; j++) s += g_degp[i*4 + j];
    g_dinv[i] = rsqrtf(s);
}

// ============================================================================
// Kernel 3: Z = dinv ⊙ (In @ W^T).  K=128, 4 chunks, double-buffered.
// Epilogue: smem-staged transpose -> fully coalesced Z^T plane stores.
// ============================================================================
#define GW_PITCH 40
#define GW_TILE  (128*GW_PITCH)
#define GW_STAGE (2*GW_TILE)
#define GW_SMEM  (2*GW_STAGE*4)         // 81920 B
#define TP 264                          // transpose pitch (bf16): [128 hi | 128 lo | 8 pad]

__global__ void __launch_bounds__(256,2) k_gemmw(const float* __restrict__ xin,
                                                 const float* __restrict__ W,
                                                 int use_internal)
{
    extern __shared__ float sm[];
    const uint32_t smb = smem_u32(sm);
    const float* __restrict__ in = use_internal ? g_y : xin;
    const int tid = threadIdx.x, lane = tid & 31, wid = tid >> 5;
    const int wy = wid >> 2, wx = wid & 3;
    const int rbase = blockIdx.x*128;

    auto copy = [&](int c){
        const uint32_t ab = smb + (uint32_t)(c & 1)*GW_STAGE*4;
        const uint32_t bb = ab + GW_TILE*4;
        #pragma unroll
        for (int r = 0; r < 4; r++){
            int id = r*256 + tid;
            int m = id >> 3, f = id & 7;
            cpa16(ab + m*160 + f*16, in + (size_t)(rbase + m)*128 + c*32 + f*4);
            cpa16(bb + m*160 + f*16, W  + (size_t)m*128          + c*32 + f*4);
        }
        CP_COMMIT();
    };

    float c4[4][4][4] = {};
    copy(0);
    for (int c = 0; c < 4; c++){
        if (c < 3){ copy(c + 1); CP_WAIT(1); } else { CP_WAIT(0); }
        __syncthreads();
        const float* As = sm + (c & 1)*GW_STAGE;
        const float* Bs = As + GW_TILE;
        #pragma unroll
        for (int kk = 0; kk < 32; kk += 16)
            mma_step_f32<GW_PITCH, GW_PITCH>(As, Bs, kk, wy, wx, lane, c4);
        __syncthreads();
    }

    const int g = lane >> 2, t = lane & 3;
    const int gb = rbase >> 10;
    const int nbase = rbase & 1023;
    __nv_bfloat16* tb = (__nv_bfloat16*)sm;   // reuse stage smem: 128 x TP bf16

    #pragma unroll
    for (int i = 0; i < 4; i++){
        #pragma unroll
        for (int h = 0; h < 2; h++){
            const int lrow = wy*64 + i*16 + g + h*8;
            const float sc = g_dinv[rbase + lrow];
            float* zr = g_z + (size_t)(rbase + lrow)*128;
            #pragma unroll
            for (int j = 0; j < 4; j++){
                const int col = wx*32 + j*8 + 2*t;
                float v0 = sc*c4[i][j][h*2], v1 = sc*c4[i][j][h*2+1];
                *(float2*)&zr[col] = make_float2(v0, v1);
                __nv_bfloat16 h0 = __float2bfloat16(v0);
                __nv_bfloat16 h1 = __float2bfloat16(v1);
                tb[(col    )*TP + lrow]       = h0;
                tb[(col + 1)*TP + lrow]       = h1;
                tb[(col    )*TP + 128 + lrow] = __float2bfloat16(v0 - __bfloat162float(h0));
                tb[(col + 1)*TP + 128 + lrow] = __float2bfloat16(v1 - __bfloat162float(h1));
            }
        }
    }
    __syncthreads();

    #pragma unroll
    for (int r = 0; r < 16; r++){
        int id = r*256 + tid;
        int plane = id >> 11, rem = id & 2047;
        int d = rem >> 4, f = rem & 15;
        uint4 v = *(const uint4*)&tb[d*TP + plane*128 + f*8];
        __nv_bfloat16* dstp = (plane ? g_ztl : g_zth) + ((size_t)gb*DF + d)*MN + nbase + f*8;
        *(uint4*)dstp = v;
    }
}

// ============================================================================
// Kernel 4: propagation.  out = relu(dinv⊙(S@Z + Z)).  K=1024: 32 chunks k32.
// 3-stage cp.async, ONE barrier per chunk, ldmatrix fragment loads.
// Interleaved hi/lo rows: [32 hi | 32 lo | 8 pad] bf16 = 144 B.
// grid (8 mt, 32 g), 256 threads, 2 CTAs/SM.
// ============================================================================
#define PR_PITCH 72
#define PR_MAT   (128*PR_PITCH)         // 9216 elems = 18432 B
#define PR_STAGE (2*PR_MAT)             // S + Zt = 36864 B
#define PR_NSTG  3
#define PR_SMEM  (PR_NSTG*PR_STAGE*2)   // 110592 B

__global__ void __launch_bounds__(256,2) k_prop(float* __restrict__ outext, int to_internal)
{
    extern __shared__ __nv_bfloat16 smh[];
    const uint32_t smb = smem_u32(smh);
    const int tid = threadIdx.x, lane = tid & 31, wid = tid >> 5;
    const int wy = wid >> 2, wx = wid & 3;
    const int mt = blockIdx.x, gb = blockIdx.y;
    float* __restrict__ dst = to_internal ? g_y : outext;

    const int mrow0 = gb*MN + mt*128;

    // coverage: 2 mats x 128 rows x 8 ops(16B) = 2048 = 8 rounds x 256 thr
    auto copy = [&](int c){
        const uint32_t sb = smb + (uint32_t)(c % PR_NSTG)*PR_STAGE*2;
        #pragma unroll
        for (int r = 0; r < 8; r++){
            int id = r*256 + tid;
            int mat = id >> 10, rem = id & 1023;
            int row = rem >> 3, o = rem & 7;
            int half = o >> 2, f = o & 3;
            const uint32_t dsta = sb + mat*(PR_MAT*2) + row*144 + half*64 + f*16;
            const __nv_bfloat16* src;
            if (mat == 0) src = (half ? g_Sl : g_Sh) + (size_t)(mrow0 + row)*MN + c*32 + f*8;
            else          src = (half ? g_ztl : g_zth) + ((size_t)gb*DF + row)*MN + c*32 + f*8;
            cpa16(dsta, src);
        }
        CP_COMMIT();
    };

    float c4[4][4][4] = {};
    copy(0); copy(1);
    for (int c = 0; c < 32; c++){
        if (c < 31) { CP_WAIT(1); } else { CP_WAIT(0); }
        __syncthreads();   // single barrier: stage (c+2)%3's readers (chunk c-1) passed here
        const uint32_t A = smb + (uint32_t)(c % PR_NSTG)*PR_STAGE*2;
        const uint32_t B = A + PR_MAT*2;
        #pragma unroll
        for (int kk = 0; kk < 32; kk += 16)
            mma_step_ldsm<PR_PITCH>(A, B, 64, 64, kk, wy, wx, lane, c4);
        if (c + 2 < 32) copy(c + 2);
    }

    const int g = lane >> 2, t = lane & 3;
    #pragma unroll
    for (int i = 0; i < 4; i++){
        #pragma unroll
        for (int h = 0; h < 2; h++){
            const int row = mrow0 + wy*64 + i*16 + g + h*8;
            const float sc = g_dinv[row];
            const float* zr = g_z + (size_t)row*128;
            float* orow = dst + (size_t)row*128;
            #pragma unroll
            for (int j = 0; j < 4; j++){
                const int col = wx*32 + j*8 + 2*t;
                float2 z = *(const float2*)&zr[col];
                float2 o;
                o.x = fmaxf(sc*(c4[i][j][h*2]   + z.x), 0.f);
                o.y = fmaxf(sc*(c4[i][j][h*2+1] + z.y), 0.f);
                *(float2*)&orow[col] = o;
            }
        }
    }
}

// ============================================================================
extern "C" void kernel_launch(void* const* d_in, const int* in_sizes, int n_in,
                              void* d_out, int out_size)
{
    (void)in_sizes; (void)n_in; (void)out_size;
    const float* X  = (const float*)d_in[0];
    const float* E  = (const float*)d_in[1];
    const float* W1 = (const float*)d_in[2];
    const float* W2 = (const float*)d_in[3];
    float* out = (float*)d_out;

    cudaFuncSetAttribute(k_sbuild, cudaFuncAttributeMaxDynamicSharedMemorySize, SB_SMEM);
    cudaFuncSetAttribute(k_gemmw,  cudaFuncAttributeMaxDynamicSharedMemorySize, GW_SMEM);
    cudaFuncSetAttribute(k_prop,   cudaFuncAttributeMaxDynamicSharedMemorySize, PR_SMEM);

    k_esplit<<<2048, 256>>>(E);
    k_sbuild<<<dim3(8, 32), 256, SB_SMEM>>>();
    k_dinv  <<<NROWS/256, 256>>>();
    k_gemmw <<<256, 256, GW_SMEM>>>(X, W1, 0);
    k_prop  <<<dim3(8, 32), 256, PR_SMEM>>>(nullptr, 1);
    k_gemmw <<<256, 256, GW_SMEM>>>(nullptr, W2, 1);
    k_prop  <<<dim3(8, 32), 256, PR_SMEM>>>(out, 0);
}